// round 12
// baseline (speedup 1.0000x reference)
#include <cuda_runtime.h>
#include <cuda_fp16.h>
#include <cstdint>

// ---------------------------------------------------------------------------
// Problem constants
// ---------------------------------------------------------------------------
#define Dm    512
#define Hh    8
#define DHh   64
#define DFFm  2048
#define Kk    4
#define Ss    4
#define Bb    4
#define LQ    4165
#define NTOK  (Bb * LQ)     // 16660
#define MVOA  896           // merged V(512) + OFF(256) + ATT(128)
#define MOA2  384           // OFF+ATT width

__device__ __constant__ int c_wl[4]   = {56, 28, 14, 7};
__device__ __constant__ int c_hl[4]   = {56, 28, 14, 7};
__device__ __constant__ int c_offs[4] = {0, 3136, 3920, 4116};

// ---------------------------------------------------------------------------
// Scratch
// ---------------------------------------------------------------------------
__device__ float g_REF [(size_t)NTOK * 2];
__device__ float g_OA  [(size_t)NTOK * MOA2];   // OFF | ATT logits (fp32)
__device__ float g_ball[MVOA];

// fp16 buffers
__device__ __half g_Qh  [(size_t)NTOK * Dm];
__device__ __half g_Vh  [(size_t)NTOK * Dm];
__device__ __half g_ACCh[(size_t)NTOK * Dm];
__device__ __half g_A2h [(size_t)NTOK * Dm];
__device__ __half g_Xh  [(size_t)NTOK * Dm];
__device__ __half g_Hbh [(size_t)NTOK * DFFm];
__device__ __half g_Yh  [(size_t)NTOK * Dm];
__device__ __half g_Wah [(size_t)Dm * MVOA];
__device__ __half g_Woh [(size_t)Dm * Dm];
__device__ __half g_W1h [(size_t)Dm * DFFm];
__device__ __half g_W2h [(size_t)DFFm * Dm];

// ---------------------------------------------------------------------------
__device__ __forceinline__ int scale_of(int p, int& loc) {
    if (p < 3136)      { loc = p;        return 0; }
    else if (p < 3920) { loc = p - 3136; return 1; }
    else if (p < 4116) { loc = p - 3920; return 2; }
    else               { loc = p - 4116; return 3; }
}

// ---------------------------------------------------------------------------
// pack: srcs -> Qh fp16; refs -> REF (folded)
// ---------------------------------------------------------------------------
__global__ void pack_kernel(const float* __restrict__ s0, const float* __restrict__ s1,
                            const float* __restrict__ s2, const float* __restrict__ s3,
                            const float* __restrict__ r0, const float* __restrict__ r1,
                            const float* __restrict__ r2, const float* __restrict__ r3,
                            __half* __restrict__ Qh, float* __restrict__ REF)
{
    int e = blockIdx.x * blockDim.x + threadIdx.x;
    const int total = NTOK * (Dm / 4);
    if (e >= total) return;
    int n  = e >> 7;
    int d4 = e & 127;
    int b = n / LQ;
    int p = n % LQ;
    int loc;
    int l = scale_of(p, loc);
    const float* src = (l == 0) ? s0 : (l == 1) ? s1 : (l == 2) ? s2 : s3;
    int lq = c_wl[l] * c_hl[l];
    float4 v = reinterpret_cast<const float4*>(src)[(size_t)(b * lq + loc) * 128 + d4];
    __half h[4] = {__float2half(v.x), __float2half(v.y), __float2half(v.z), __float2half(v.w)};
    *reinterpret_cast<uint2*>(Qh + (size_t)n * Dm + d4 * 4) = *reinterpret_cast<uint2*>(h);

    if (e < NTOK) {
        int nb = e / LQ, pp = e % LQ, lc;
        int ll = scale_of(pp, lc);
        const float* rsrc = (ll == 0) ? r0 : (ll == 1) ? r1 : (ll == 2) ? r2 : r3;
        int lq2 = c_wl[ll] * c_hl[ll];
        float2 rv = *reinterpret_cast<const float2*>(rsrc + (size_t)(nb * lq2 + lc) * 2);
        *reinterpret_cast<float2*>(REF + (size_t)e * 2) = rv;
    }
}

// merge Wv/Woff/Wattn -> fp16 [512, 896] (+ merged fp32 bias)
__global__ void merge_h_kernel(const float* __restrict__ Wv, const float* __restrict__ Woff,
                               const float* __restrict__ Wattn,
                               const float* __restrict__ bv, const float* __restrict__ boff,
                               const float* __restrict__ battn,
                               __half* __restrict__ Wah, float* __restrict__ ball)
{
    int i = blockIdx.x * blockDim.x + threadIdx.x;
    if (i < Dm * MVOA) {
        int r = i / MVOA, c = i % MVOA;
        float w;
        if (c < 512)       w = Wv[r * 512 + c];
        else if (c < 768)  w = Woff[r * 256 + (c - 512)];
        else               w = Wattn[r * 128 + (c - 768)];
        Wah[i] = __float2half(w);
    }
    if (i < MVOA)
        ball[i] = (i < 512) ? bv[i] : (i < 768) ? boff[i - 512] : battn[i - 768];
}

// single kernel converting W1, W2, Wo -> fp16
#define N_W1 (Dm * DFFm)
#define N_W2 (DFFm * Dm)
#define N_WO (Dm * Dm)
__global__ void conv_all_kernel(const float* __restrict__ W1, const float* __restrict__ W2,
                                const float* __restrict__ Wo,
                                __half* __restrict__ W1h, __half* __restrict__ W2h,
                                __half* __restrict__ Woh)
{
    int i = blockIdx.x * blockDim.x + threadIdx.x;
    if (i < N_W1)                    W1h[i] = __float2half(W1[i]);
    else if (i < N_W1 + N_W2)        W2h[i - N_W1] = __float2half(W2[i - N_W1]);
    else if (i < N_W1 + N_W2 + N_WO) Woh[i - N_W1 - N_W2] = __float2half(Wo[i - N_W1 - N_W2]);
}

// ---------------------------------------------------------------------------
// fp16 GEMM via mma.sync.m16n8k16, BK=64 k-tiles, 3-stage cp.async pipeline.
// Block tile 128x128, 8 warps (64x32 each). 4 ks sub-iterations per tile.
// A stage: 128 rows x 64 cols fp16, row stride 144B -> 18432B.
// B stage: 64 rows x 128 cols fp16, row stride 272B -> 17408B.
// MODE 0: fp32 out. MODE 1: relu->fp16. MODE 3: fp16.
// MODE 2: colBase<512 -> fp16 Vh; else fp32 OA.
// ---------------------------------------------------------------------------
#define LDSM4(r, addr) \
    asm volatile("ldmatrix.sync.aligned.m8n8.x4.shared.b16 {%0,%1,%2,%3}, [%4];" \
                 : "=r"((r)[0]), "=r"((r)[1]), "=r"((r)[2]), "=r"((r)[3]) : "r"(addr))
#define LDSM4T(r, addr) \
    asm volatile("ldmatrix.sync.aligned.m8n8.x4.trans.shared.b16 {%0,%1,%2,%3}, [%4];" \
                 : "=r"((r)[0]), "=r"((r)[1]), "=r"((r)[2]), "=r"((r)[3]) : "r"(addr))
#define MMA16816H(c, a, b) \
    asm volatile("mma.sync.aligned.m16n8k16.row.col.f32.f16.f16.f32 " \
                 "{%0,%1,%2,%3}, {%4,%5,%6,%7}, {%8,%9}, {%0,%1,%2,%3};" \
                 : "+f"((c)[0]), "+f"((c)[1]), "+f"((c)[2]), "+f"((c)[3]) \
                 : "r"((a)[0]), "r"((a)[1]), "r"((a)[2]), "r"((a)[3]), \
                   "r"((b)[0]), "r"((b)[1]))

#define A_STAGE     18432            // 128 * 144
#define B_STAGE     17408            // 64 * 272
#define STAGE_BYTES (A_STAGE + B_STAGE)   // 35840
#define SMEM_GEMM   (3 * STAGE_BYTES)     // 107520

template<int MODE>
__global__ __launch_bounds__(256, 2)
void gemm_fp16_kernel(const __half* __restrict__ A,
                      const __half* __restrict__ W,
                      const float* __restrict__ bias, void* __restrict__ Cout,
                      void* __restrict__ Cout2,
                      int N, int K, int M)
{
    extern __shared__ char smem[];
    const uint32_t sdata = (uint32_t)__cvta_generic_to_shared(smem);

    const int tid  = threadIdx.x;
    const int lane = tid & 31;
    const int wid  = tid >> 5;
    const int wm = (wid & 1) * 64;
    const int wn = (wid >> 1) * 32;
    const int rowBase = blockIdx.y * 128;
    const int colBase = blockIdx.x * 128;

    const int lrowA = lane & 15;
    const int lcolA = (lane >> 4) * 8;
    const uint32_t aFragOff = (uint32_t)((wm + lrowA) * 144 + lcolA * 2);
    const int grp = lane >> 3;
    const int rB  = lane & 7;
    const uint32_t bFragOff = (uint32_t)(A_STAGE + ((grp & 1) * 8 + rB) * 272 + (grp >> 1) * 16 + wn * 2);

    const int T = K >> 6;   // BK=64

    float acc[4][4][4];
#pragma unroll
    for (int i = 0; i < 4; i++)
#pragma unroll
        for (int j = 0; j < 4; j++)
#pragma unroll
            for (int r = 0; r < 4; r++) acc[i][j][r] = 0.f;

    auto loadStage = [&](int t, int stage) {
        int kp0 = t << 6;
        uint32_t sb = sdata + stage * STAGE_BYTES;
        // A: 128 rows x 64 cols (128B/row), 4 chunks of 16B per thread
#pragma unroll
        for (int i = 0; i < 4; i++) {
            int id = tid * 4 + i;
            int r = id >> 3, c = id & 7;
            int gr = rowBase + r;
            const void* src = (const void*)(A + (size_t)gr * K + kp0 + c * 8);
            uint32_t dst = sb + r * 144 + c * 16;
            int sz = (gr < N) ? 16 : 0;
            asm volatile("cp.async.cg.shared.global [%0], [%1], 16, %2;"
                         :: "r"(dst), "l"(src), "r"(sz));
        }
        // B: 64 rows x 128 cols (256B/row), 4 chunks per thread
#pragma unroll
        for (int i = 0; i < 4; i++) {
            int id = tid * 4 + i;
            int r = id >> 4, c = id & 15;
            const void* src = (const void*)(W + (size_t)(kp0 + r) * M + colBase + c * 8);
            uint32_t dst = sb + A_STAGE + r * 272 + c * 16;
            asm volatile("cp.async.cg.shared.global [%0], [%1], 16;"
                         :: "r"(dst), "l"(src));
        }
        asm volatile("cp.async.commit_group;" ::: "memory");
    };

    loadStage(0, 0);
    if (T > 1) loadStage(1, 1);

    for (int t = 0; t < T; t++) {
        if (t + 1 < T) asm volatile("cp.async.wait_group 1;" ::: "memory");
        else           asm volatile("cp.async.wait_group 0;" ::: "memory");
        __syncthreads();

        if (t + 2 < T) loadStage(t + 2, (t + 2) % 3);

        uint32_t sb = sdata + (t % 3) * STAGE_BYTES;
        uint32_t aBase = sb + aFragOff;
        uint32_t bBase = sb + bFragOff;
#pragma unroll
        for (int ks = 0; ks < 4; ks++) {
            uint32_t af[4][4];
            uint32_t bfr[4][2];
            uint32_t aB = aBase + ks * 32;        // ks*16 cols * 2B
            uint32_t bB = bBase + ks * 4352;      // ks*16 rows * 272B
#pragma unroll
            for (int mt = 0; mt < 4; mt++) LDSM4(af[mt], aB + mt * 2304);   // 16 rows * 144B
#pragma unroll
            for (int np = 0; np < 2; np++) {
                uint32_t r4[4];
                LDSM4T(r4, bB + np * 32);
                bfr[np * 2][0] = r4[0]; bfr[np * 2][1] = r4[1];
                bfr[np * 2 + 1][0] = r4[2]; bfr[np * 2 + 1][1] = r4[3];
            }
#pragma unroll
            for (int mt = 0; mt < 4; mt++)
#pragma unroll
                for (int nt = 0; nt < 4; nt++)
                    MMA16816H(acc[mt][nt], af[mt], bfr[nt]);
        }
    }

    // epilogue
    const int mr = lane >> 2;
    const int nc = (lane & 3) * 2;
    const bool vpart = (MODE == 2) && (colBase < 512);

#pragma unroll
    for (int mt = 0; mt < 4; mt++) {
#pragma unroll
        for (int nt = 0; nt < 4; nt++) {
            int n0 = colBase + wn + nt * 8 + nc;
            float bb0 = bias[n0], bb1 = bias[n0 + 1];
#pragma unroll
            for (int half = 0; half < 2; half++) {
                int m = rowBase + wm + mt * 16 + mr + half * 8;
                if (m >= N) continue;
                float v0 = acc[mt][nt][half * 2 + 0] + bb0;
                float v1 = acc[mt][nt][half * 2 + 1] + bb1;
                if (MODE == 0) {
                    *reinterpret_cast<float2*>((float*)Cout + (size_t)m * M + n0) = make_float2(v0, v1);
                } else if (MODE == 1 || MODE == 3) {
                    if (MODE == 1) { v0 = fmaxf(v0, 0.f); v1 = fmaxf(v1, 0.f); }
                    __half2 hv; hv.x = __float2half(v0); hv.y = __float2half(v1);
                    *reinterpret_cast<__half2*>((__half*)Cout + (size_t)m * M + n0) = hv;
                } else {
                    if (vpart) {
                        __half2 hv; hv.x = __float2half(v0); hv.y = __float2half(v1);
                        *reinterpret_cast<__half2*>((__half*)Cout + (size_t)m * Dm + n0) = hv;
                    } else {
                        *reinterpret_cast<float2*>((float*)Cout2 + (size_t)m * MOA2 + (n0 - 512)) = make_float2(v0, v1);
                    }
                }
            }
        }
    }
}

// ---------------------------------------------------------------------------
// Deformable sampling with fused softmax (R10 branchy gathers — fastest form).
// ---------------------------------------------------------------------------
__global__ void sample_kernel(const __half* __restrict__ Vh, const float* __restrict__ OA,
                              const float* __restrict__ REF, __half* __restrict__ ACCh)
{
    int wid = blockIdx.x * (blockDim.x / 32) + (threadIdx.x / 32);
    if (wid >= NTOK * Hh) return;
    int lane = threadIdx.x & 31;
    int n = wid / Hh;
    int h = wid % Hh;
    int b = n / LQ;

    float refx = REF[(size_t)n * 2 + 0];
    float refy = REF[(size_t)n * 2 + 1];
    const float* offp = OA + (size_t)n * MOA2;
    const float* attp = OA + (size_t)n * MOA2 + 256 + h * 16;

    float lg[16], mx = -1e30f;
#pragma unroll
    for (int i = 0; i < 16; i += 4) {
        float4 l4 = *reinterpret_cast<const float4*>(attp + i);
        lg[i] = l4.x; lg[i + 1] = l4.y; lg[i + 2] = l4.z; lg[i + 3] = l4.w;
    }
#pragma unroll
    for (int i = 0; i < 16; i++) mx = fmaxf(mx, lg[i]);
    float ssum = 0.f;
#pragma unroll
    for (int i = 0; i < 16; i++) { lg[i] = expf(lg[i] - mx); ssum += lg[i]; }
    float sinv = 1.f / ssum;

    float acc0 = 0.f, acc1 = 0.f;

#pragma unroll
    for (int s = 0; s < Ss; s++) {
        int wl = c_wl[s], hl = c_hl[s];
        int base_tok = b * LQ + c_offs[s];
        float fwl = (float)wl, fhl = (float)hl;
#pragma unroll
        for (int k = 0; k < Kk; k++) {
            float w  = lg[s * 4 + k] * sinv;
            float ox = offp[(((h * 4 + s) * 4 + k) * 2) + 0];
            float oy = offp[(((h * 4 + s) * 4 + k) * 2) + 1];
            float x = refx * fwl + ox - 0.5f;
            float y = refy * fhl + oy - 0.5f;
            float x0f = floorf(x), y0f = floorf(y);
            int x0 = (int)x0f, y0 = (int)y0f;
            float wx1 = x - x0f, wx0 = 1.f - wx1;
            float wy1 = y - y0f, wy0 = 1.f - wy1;
#pragma unroll
            for (int c = 0; c < 4; c++) {
                int xi = x0 + (c & 1);
                int yi = y0 + (c >> 1);
                float wc = ((c & 1) ? wx1 : wx0) * ((c >> 1) ? wy1 : wy0);
                bool valid = (xi >= 0) && (xi < wl) && (yi >= 0) && (yi < hl);
                if (valid) {
                    int idx = yi * wl + xi;
                    const __half2* vp = reinterpret_cast<const __half2*>(
                        Vh + ((size_t)(base_tok + idx) * Dm + h * DHh));
                    float ww = w * wc;
                    __half2 hv = __ldg(vp + lane);
                    float2 fv = __half22float2(hv);
                    acc0 = fmaf(ww, fv.x, acc0);
                    acc1 = fmaf(ww, fv.y, acc1);
                }
            }
        }
    }
    size_t base = (size_t)n * Dm + h * DHh;
    __half2 hv; hv.x = __float2half(acc0); hv.y = __float2half(acc1);
    *reinterpret_cast<__half2*>(ACCh + base + 2 * lane) = hv;
}

// ---------------------------------------------------------------------------
// Fused residual-add + LayerNorm, fp16 inputs; fp16 and/or fp32 outputs.
// ---------------------------------------------------------------------------
__global__ void add_layernorm_h_kernel(const __half* __restrict__ A, const __half* __restrict__ Bv,
                                       const float* __restrict__ g, const float* __restrict__ be,
                                       __half* __restrict__ outh, float* __restrict__ outf)
{
    int n = blockIdx.x;
    int t = threadIdx.x;
    float v[4];
    float s = 0.f, ss = 0.f;
    const __half2* a2 = reinterpret_cast<const __half2*>(A + (size_t)n * Dm);
    const __half2* b2 = reinterpret_cast<const __half2*>(Bv + (size_t)n * Dm);
#pragma unroll
    for (int i = 0; i < 2; i++) {
        int d2 = t + i * 128;
        float2 fa = __half22float2(a2[d2]);
        float2 fb = __half22float2(b2[d2]);
        float x0 = fa.x + fb.x, x1 = fa.y + fb.y;
        v[i * 2] = x0; v[i * 2 + 1] = x1;
        s += x0 + x1; ss += x0 * x0 + x1 * x1;
    }
#pragma unroll
    for (int o = 16; o > 0; o >>= 1) {
        s  += __shfl_xor_sync(0xffffffffu, s,  o);
        ss += __shfl_xor_sync(0xffffffffu, ss, o);
    }
    __shared__ float sh[8];
    int w = t >> 5, ln = t & 31;
    if (ln == 0) { sh[w] = s; sh[4 + w] = ss; }
    __syncthreads();
    float ts  = sh[0] + sh[1] + sh[2] + sh[3];
    float tss = sh[4] + sh[5] + sh[6] + sh[7];
    float mu  = ts * (1.f / Dm);
    float var = tss * (1.f / Dm) - mu * mu;
    float inv = rsqrtf(var + 1e-5f);
#pragma unroll
    for (int i = 0; i < 2; i++) {
        int d2 = t + i * 128;
        int d = d2 * 2;
        float o0 = (v[i * 2]     - mu) * inv * g[d]     + be[d];
        float o1 = (v[i * 2 + 1] - mu) * inv * g[d + 1] + be[d + 1];
        if (outh) {
            __half2 hv; hv.x = __float2half(o0); hv.y = __float2half(o1);
            *reinterpret_cast<__half2*>(outh + (size_t)n * Dm + d) = hv;
        }
        if (outf) {
            *reinterpret_cast<float2*>(outf + (size_t)n * Dm + d) = make_float2(o0, o1);
        }
    }
}

// ---------------------------------------------------------------------------
// Launch
// ---------------------------------------------------------------------------
extern "C" void kernel_launch(void* const* d_in, const int* in_sizes, int n_in,
                              void* d_out, int out_size)
{
    const float* srcs[4] = {nullptr, nullptr, nullptr, nullptr};
    const float* refs[4] = {nullptr, nullptr, nullptr, nullptr};
    const int src_sz[4] = {Bb * 56 * 56 * Dm, Bb * 28 * 28 * Dm, Bb * 14 * 14 * Dm, Bb * 7 * 7 * Dm};
    const int ref_sz[4] = {Bb * 56 * 56 * 2,  Bb * 28 * 28 * 2,  Bb * 14 * 14 * 2,  Bb * 7 * 7 * 2};
    for (int i = 0; i < 8; i++) {
        int sz = in_sizes[i];
        for (int l = 0; l < 4; l++) {
            if (sz == src_sz[l] && !srcs[l]) { srcs[l] = (const float*)d_in[i]; goto next; }
        }
        for (int l = 0; l < 4; l++) {
            if (sz == ref_sz[l] && !refs[l]) { refs[l] = (const float*)d_in[i]; goto next; }
        }
    next:;
    }

    const float* Wv    = (const float*)d_in[8];
    const float* bv    = (const float*)d_in[9];
    const float* Woff  = (const float*)d_in[10];
    const float* boff  = (const float*)d_in[11];
    const float* Wattn = (const float*)d_in[12];
    const float* battn = (const float*)d_in[13];
    const float* Wo    = (const float*)d_in[14];
    const float* bo    = (const float*)d_in[15];
    const float* W1    = (const float*)d_in[16];
    const float* b1    = (const float*)d_in[17];
    const float* W2    = (const float*)d_in[18];
    const float* b2    = (const float*)d_in[19];
    const float* g1    = (const float*)d_in[20];
    const float* be1   = (const float*)d_in[21];
    const float* g2    = (const float*)d_in[22];
    const float* be2   = (const float*)d_in[23];
    float* out = (float*)d_out;

    float *REF, *OA, *ball;
    __half *Qh, *Vh, *ACCh, *A2h, *Xh, *Hbh, *Yh, *Wah, *Woh, *W1h, *W2h;
    cudaGetSymbolAddress((void**)&REF,  g_REF);
    cudaGetSymbolAddress((void**)&OA,   g_OA);
    cudaGetSymbolAddress((void**)&ball, g_ball);
    cudaGetSymbolAddress((void**)&Qh,   g_Qh);
    cudaGetSymbolAddress((void**)&Vh,   g_Vh);
    cudaGetSymbolAddress((void**)&ACCh, g_ACCh);
    cudaGetSymbolAddress((void**)&A2h,  g_A2h);
    cudaGetSymbolAddress((void**)&Xh,   g_Xh);
    cudaGetSymbolAddress((void**)&Hbh,  g_Hbh);
    cudaGetSymbolAddress((void**)&Yh,   g_Yh);
    cudaGetSymbolAddress((void**)&Wah,  g_Wah);
    cudaGetSymbolAddress((void**)&Woh,  g_Woh);
    cudaGetSymbolAddress((void**)&W1h,  g_W1h);
    cudaGetSymbolAddress((void**)&W2h,  g_W2h);

    cudaFuncSetAttribute(gemm_fp16_kernel<0>, cudaFuncAttributeMaxDynamicSharedMemorySize, SMEM_GEMM);
    cudaFuncSetAttribute(gemm_fp16_kernel<1>, cudaFuncAttributeMaxDynamicSharedMemorySize, SMEM_GEMM);
    cudaFuncSetAttribute(gemm_fp16_kernel<2>, cudaFuncAttributeMaxDynamicSharedMemorySize, SMEM_GEMM);
    cudaFuncSetAttribute(gemm_fp16_kernel<3>, cudaFuncAttributeMaxDynamicSharedMemorySize, SMEM_GEMM);

    const int rowBlocks = (NTOK + 127) / 128;   // 131
    dim3 blk(256);

    // 0: merged VOA weight
    merge_h_kernel<<<(Dm * MVOA + 255) / 256, 256>>>(Wv, Woff, Wattn, bv, boff, battn, Wah, ball);
    // 1: all other weight converts (one kernel)
    {
        int total = N_W1 + N_W2 + N_WO;
        conv_all_kernel<<<(total + 255) / 256, 256>>>(W1, W2, Wo, W1h, W2h, Woh);
    }
    // 2: pack (Q + REF folded)
    {
        int total = NTOK * (Dm / 4);
        pack_kernel<<<(total + 255) / 256, 256>>>(srcs[0], srcs[1], srcs[2], srcs[3],
                                                  refs[0], refs[1], refs[2], refs[3], Qh, REF);
    }
    // 3: [Vh | OA] = Q @ [Wv|Woff|Wattn] + bias
    gemm_fp16_kernel<2><<<dim3(MVOA / 128, rowBlocks), blk, SMEM_GEMM>>>(Qh, Wah, ball, Vh, OA, NTOK, Dm, MVOA);
    // 4: sampling (fused softmax) -> ACCh
    {
        int warps = NTOK * Hh;
        sample_kernel<<<(warps + 7) / 8, 256>>>(Vh, OA, REF, ACCh);
    }
    // 5: A2h = ACC @ Wo + bo  (fp16 out)
    gemm_fp16_kernel<3><<<dim3(Dm / 128, rowBlocks), blk, SMEM_GEMM>>>(ACCh, Woh, bo, A2h, nullptr, NTOK, Dm, Dm);
    // 6: Xh = LN(Qh + A2h)
    add_layernorm_h_kernel<<<NTOK, 128>>>(Qh, A2h, g1, be1, Xh, nullptr);
    // 7: Hbh = fp16(relu(X @ W1 + b1))
    gemm_fp16_kernel<1><<<dim3(DFFm / 128, rowBlocks), blk, SMEM_GEMM>>>(Xh, W1h, b1, Hbh, nullptr, NTOK, Dm, DFFm);
    // 8: Yh = Hb @ W2 + b2  (fp16 out)
    gemm_fp16_kernel<3><<<dim3(Dm / 128, rowBlocks), blk, SMEM_GEMM>>>(Hbh, W2h, b2, Yh, nullptr, NTOK, DFFm, Dm);
    // 9: out = LN(Xh + Yh)  (fp32 to d_out)
    add_layernorm_h_kernel<<<NTOK, 128>>>(Xh, Yh, g2, be2, nullptr, out);
}

// round 13
// speedup vs baseline: 1.0285x; 1.0285x over previous
#include <cuda_runtime.h>
#include <cuda_fp16.h>
#include <cstdint>

// ---------------------------------------------------------------------------
// Problem constants
// ---------------------------------------------------------------------------
#define Dm    512
#define Hh    8
#define DHh   64
#define DFFm  2048
#define Kk    4
#define Ss    4
#define Bb    4
#define LQ    4165
#define NTOK  (Bb * LQ)     // 16660
#define MVOA  896           // merged V(512) + OFF(256) + ATT(128)
#define MOA2  384           // OFF+ATT width

__device__ __constant__ int c_wl[4]   = {56, 28, 14, 7};
__device__ __constant__ int c_hl[4]   = {56, 28, 14, 7};
__device__ __constant__ int c_offs[4] = {0, 3136, 3920, 4116};

// ---------------------------------------------------------------------------
// Scratch
// ---------------------------------------------------------------------------
__device__ float g_REF [(size_t)NTOK * 2];
__device__ float g_OA  [(size_t)NTOK * MOA2];   // OFF | ATT logits (fp32)
__device__ float g_ball[MVOA];

// fp16 buffers
__device__ __half g_Qh  [(size_t)NTOK * Dm];
__device__ __half g_Vh  [(size_t)NTOK * Dm];
__device__ __half g_ACCh[(size_t)NTOK * Dm];
__device__ __half g_A2h [(size_t)NTOK * Dm];
__device__ __half g_Xh  [(size_t)NTOK * Dm];
__device__ __half g_Hbh [(size_t)NTOK * DFFm];
__device__ __half g_Yh  [(size_t)NTOK * Dm];
__device__ __half g_Wah [(size_t)Dm * MVOA];
__device__ __half g_Woh [(size_t)Dm * Dm];
__device__ __half g_W1h [(size_t)Dm * DFFm];
__device__ __half g_W2h [(size_t)DFFm * Dm];

// ---------------------------------------------------------------------------
__device__ __forceinline__ int scale_of(int p, int& loc) {
    if (p < 3136)      { loc = p;        return 0; }
    else if (p < 3920) { loc = p - 3136; return 1; }
    else if (p < 4116) { loc = p - 3920; return 2; }
    else               { loc = p - 4116; return 3; }
}

// ---------------------------------------------------------------------------
// pack: srcs -> Qh fp16; refs -> REF (folded)
// ---------------------------------------------------------------------------
__global__ void pack_kernel(const float* __restrict__ s0, const float* __restrict__ s1,
                            const float* __restrict__ s2, const float* __restrict__ s3,
                            const float* __restrict__ r0, const float* __restrict__ r1,
                            const float* __restrict__ r2, const float* __restrict__ r3,
                            __half* __restrict__ Qh, float* __restrict__ REF)
{
    int e = blockIdx.x * blockDim.x + threadIdx.x;
    const int total = NTOK * (Dm / 4);
    if (e >= total) return;
    int n  = e >> 7;
    int d4 = e & 127;
    int b = n / LQ;
    int p = n % LQ;
    int loc;
    int l = scale_of(p, loc);
    const float* src = (l == 0) ? s0 : (l == 1) ? s1 : (l == 2) ? s2 : s3;
    int lq = c_wl[l] * c_hl[l];
    float4 v = reinterpret_cast<const float4*>(src)[(size_t)(b * lq + loc) * 128 + d4];
    __half h[4] = {__float2half(v.x), __float2half(v.y), __float2half(v.z), __float2half(v.w)};
    *reinterpret_cast<uint2*>(Qh + (size_t)n * Dm + d4 * 4) = *reinterpret_cast<uint2*>(h);

    if (e < NTOK) {
        int nb = e / LQ, pp = e % LQ, lc;
        int ll = scale_of(pp, lc);
        const float* rsrc = (ll == 0) ? r0 : (ll == 1) ? r1 : (ll == 2) ? r2 : r3;
        int lq2 = c_wl[ll] * c_hl[ll];
        float2 rv = *reinterpret_cast<const float2*>(rsrc + (size_t)(nb * lq2 + lc) * 2);
        *reinterpret_cast<float2*>(REF + (size_t)e * 2) = rv;
    }
}

// merge Wv/Woff/Wattn -> fp16 [512, 896] (+ merged fp32 bias)
__global__ void merge_h_kernel(const float* __restrict__ Wv, const float* __restrict__ Woff,
                               const float* __restrict__ Wattn,
                               const float* __restrict__ bv, const float* __restrict__ boff,
                               const float* __restrict__ battn,
                               __half* __restrict__ Wah, float* __restrict__ ball)
{
    int i = blockIdx.x * blockDim.x + threadIdx.x;
    if (i < Dm * MVOA) {
        int r = i / MVOA, c = i % MVOA;
        float w;
        if (c < 512)       w = Wv[r * 512 + c];
        else if (c < 768)  w = Woff[r * 256 + (c - 512)];
        else               w = Wattn[r * 128 + (c - 768)];
        Wah[i] = __float2half(w);
    }
    if (i < MVOA)
        ball[i] = (i < 512) ? bv[i] : (i < 768) ? boff[i - 512] : battn[i - 768];
}

// single kernel converting W1, W2, Wo -> fp16
#define N_W1 (Dm * DFFm)
#define N_W2 (DFFm * Dm)
#define N_WO (Dm * Dm)
__global__ void conv_all_kernel(const float* __restrict__ W1, const float* __restrict__ W2,
                                const float* __restrict__ Wo,
                                __half* __restrict__ W1h, __half* __restrict__ W2h,
                                __half* __restrict__ Woh)
{
    int i = blockIdx.x * blockDim.x + threadIdx.x;
    if (i < N_W1)                    W1h[i] = __float2half(W1[i]);
    else if (i < N_W1 + N_W2)        W2h[i - N_W1] = __float2half(W2[i - N_W1]);
    else if (i < N_W1 + N_W2 + N_WO) Woh[i - N_W1 - N_W2] = __float2half(Wo[i - N_W1 - N_W2]);
}

// ---------------------------------------------------------------------------
// fp16 GEMM via mma.sync.m16n8k16, 128x64 block tile, BK=32, 4-stage cp.async.
// 8 warps arranged 4 (M) x 2 (N); each warp computes 32x32.
// Low register count (~80) -> 3 CTAs/SM (24 warps) for latency hiding.
// A stage: 128 x 32 fp16, row stride 80B -> 10240B.
// B stage: 32 x 64 fp16, row stride 144B -> 4608B.
// MODE 0: fp32 out. MODE 1: relu->fp16. MODE 3: fp16.
// MODE 2: colBase<512 -> fp16 Vh; else fp32 OA.
// ---------------------------------------------------------------------------
#define LDSM4(r, addr) \
    asm volatile("ldmatrix.sync.aligned.m8n8.x4.shared.b16 {%0,%1,%2,%3}, [%4];" \
                 : "=r"((r)[0]), "=r"((r)[1]), "=r"((r)[2]), "=r"((r)[3]) : "r"(addr))
#define LDSM4T(r, addr) \
    asm volatile("ldmatrix.sync.aligned.m8n8.x4.trans.shared.b16 {%0,%1,%2,%3}, [%4];" \
                 : "=r"((r)[0]), "=r"((r)[1]), "=r"((r)[2]), "=r"((r)[3]) : "r"(addr))
#define MMA16816H(c, a, b) \
    asm volatile("mma.sync.aligned.m16n8k16.row.col.f32.f16.f16.f32 " \
                 "{%0,%1,%2,%3}, {%4,%5,%6,%7}, {%8,%9}, {%0,%1,%2,%3};" \
                 : "+f"((c)[0]), "+f"((c)[1]), "+f"((c)[2]), "+f"((c)[3]) \
                 : "r"((a)[0]), "r"((a)[1]), "r"((a)[2]), "r"((a)[3]), \
                   "r"((b)[0]), "r"((b)[1]))

#define A_STAGE     10240            // 128 * 80
#define B_STAGE     4608             // 32 * 144
#define STAGE_BYTES (A_STAGE + B_STAGE)   // 14848
#define SMEM_GEMM   (4 * STAGE_BYTES)     // 59392

template<int MODE>
__global__ __launch_bounds__(256, 3)
void gemm_fp16_kernel(const __half* __restrict__ A,
                      const __half* __restrict__ W,
                      const float* __restrict__ bias, void* __restrict__ Cout,
                      void* __restrict__ Cout2,
                      int N, int K, int M)
{
    extern __shared__ char smem[];
    const uint32_t sdata = (uint32_t)__cvta_generic_to_shared(smem);

    const int tid  = threadIdx.x;
    const int lane = tid & 31;
    const int wid  = tid >> 5;
    const int wm = (wid >> 1) * 32;      // 4 warp rows
    const int wn = (wid & 1) * 32;       // 2 warp cols
    const int rowBase = blockIdx.y * 128;
    const int colBase = blockIdx.x * 64;

    const int lrowA = lane & 15;
    const int lcolA = (lane >> 4) * 8;
    const uint32_t aFragOff = (uint32_t)((wm + lrowA) * 80 + lcolA * 2);
    const int grp = lane >> 3;
    const int rB  = lane & 7;
    const uint32_t bFragOff = (uint32_t)(A_STAGE + ((grp & 1) * 8 + rB) * 144 + (grp >> 1) * 16 + wn * 2);

    const int T = K >> 5;

    float acc[2][4][4];
#pragma unroll
    for (int i = 0; i < 2; i++)
#pragma unroll
        for (int j = 0; j < 4; j++)
#pragma unroll
            for (int r = 0; r < 4; r++) acc[i][j][r] = 0.f;

    auto loadStage = [&](int t, int stage) {
        int kp0 = t << 5;
        uint32_t sb = sdata + stage * STAGE_BYTES;
        // A: 128 rows x 32 cols (64B/row), 2 chunks of 16B per thread
#pragma unroll
        for (int i = 0; i < 2; i++) {
            int id = tid * 2 + i;
            int r = id >> 2, c = id & 3;
            int gr = rowBase + r;
            const void* src = (const void*)(A + (size_t)gr * K + kp0 + c * 8);
            uint32_t dst = sb + r * 80 + c * 16;
            int sz = (gr < N) ? 16 : 0;
            asm volatile("cp.async.cg.shared.global [%0], [%1], 16, %2;"
                         :: "r"(dst), "l"(src), "r"(sz));
        }
        // B: 32 rows x 64 cols (128B/row), 1 chunk per thread
        {
            int r = tid >> 3, c = tid & 7;
            const void* src = (const void*)(W + (size_t)(kp0 + r) * M + colBase + c * 8);
            uint32_t dst = sb + A_STAGE + r * 144 + c * 16;
            asm volatile("cp.async.cg.shared.global [%0], [%1], 16;"
                         :: "r"(dst), "l"(src));
        }
        asm volatile("cp.async.commit_group;" ::: "memory");
    };

    loadStage(0, 0);
    if (T > 1) loadStage(1, 1);
    if (T > 2) loadStage(2, 2);

    for (int t = 0; t < T; t++) {
        int rem = T - 1 - t;
        if (rem >= 2)      asm volatile("cp.async.wait_group 2;" ::: "memory");
        else if (rem == 1) asm volatile("cp.async.wait_group 1;" ::: "memory");
        else               asm volatile("cp.async.wait_group 0;" ::: "memory");
        __syncthreads();

        if (t + 3 < T) loadStage(t + 3, (t + 3) & 3);

        uint32_t sb = sdata + (t & 3) * STAGE_BYTES;
        uint32_t aBase = sb + aFragOff;
        uint32_t bBase = sb + bFragOff;
#pragma unroll
        for (int ks = 0; ks < 2; ks++) {
            uint32_t af[2][4];
            uint32_t bfr[4][2];
            uint32_t aB = aBase + ks * 32;        // ks*16 cols * 2B
            uint32_t bB = bBase + ks * 2304;      // ks*16 rows * 144B
#pragma unroll
            for (int mt = 0; mt < 2; mt++) LDSM4(af[mt], aB + mt * 1280);   // 16 rows * 80B
#pragma unroll
            for (int np = 0; np < 2; np++) {
                uint32_t r4[4];
                LDSM4T(r4, bB + np * 32);
                bfr[np * 2][0] = r4[0]; bfr[np * 2][1] = r4[1];
                bfr[np * 2 + 1][0] = r4[2]; bfr[np * 2 + 1][1] = r4[3];
            }
#pragma unroll
            for (int mt = 0; mt < 2; mt++)
#pragma unroll
                for (int nt = 0; nt < 4; nt++)
                    MMA16816H(acc[mt][nt], af[mt], bfr[nt]);
        }
    }

    // epilogue
    const int mr = lane >> 2;
    const int nc = (lane & 3) * 2;
    const bool vpart = (MODE == 2) && (colBase < 512);

#pragma unroll
    for (int mt = 0; mt < 2; mt++) {
#pragma unroll
        for (int nt = 0; nt < 4; nt++) {
            int n0 = colBase + wn + nt * 8 + nc;
            float bb0 = bias[n0], bb1 = bias[n0 + 1];
#pragma unroll
            for (int half = 0; half < 2; half++) {
                int m = rowBase + wm + mt * 16 + mr + half * 8;
                if (m >= N) continue;
                float v0 = acc[mt][nt][half * 2 + 0] + bb0;
                float v1 = acc[mt][nt][half * 2 + 1] + bb1;
                if (MODE == 0) {
                    *reinterpret_cast<float2*>((float*)Cout + (size_t)m * M + n0) = make_float2(v0, v1);
                } else if (MODE == 1 || MODE == 3) {
                    if (MODE == 1) { v0 = fmaxf(v0, 0.f); v1 = fmaxf(v1, 0.f); }
                    __half2 hv; hv.x = __float2half(v0); hv.y = __float2half(v1);
                    *reinterpret_cast<__half2*>((__half*)Cout + (size_t)m * M + n0) = hv;
                } else {
                    if (vpart) {
                        __half2 hv; hv.x = __float2half(v0); hv.y = __float2half(v1);
                        *reinterpret_cast<__half2*>((__half*)Cout + (size_t)m * Dm + n0) = hv;
                    } else {
                        *reinterpret_cast<float2*>((float*)Cout2 + (size_t)m * MOA2 + (n0 - 512)) = make_float2(v0, v1);
                    }
                }
            }
        }
    }
}

// ---------------------------------------------------------------------------
// Deformable sampling with fused softmax (branchy gathers — fastest form).
// ---------------------------------------------------------------------------
__global__ void sample_kernel(const __half* __restrict__ Vh, const float* __restrict__ OA,
                              const float* __restrict__ REF, __half* __restrict__ ACCh)
{
    int wid = blockIdx.x * (blockDim.x / 32) + (threadIdx.x / 32);
    if (wid >= NTOK * Hh) return;
    int lane = threadIdx.x & 31;
    int n = wid / Hh;
    int h = wid % Hh;
    int b = n / LQ;

    float refx = REF[(size_t)n * 2 + 0];
    float refy = REF[(size_t)n * 2 + 1];
    const float* offp = OA + (size_t)n * MOA2;
    const float* attp = OA + (size_t)n * MOA2 + 256 + h * 16;

    float lg[16], mx = -1e30f;
#pragma unroll
    for (int i = 0; i < 16; i += 4) {
        float4 l4 = *reinterpret_cast<const float4*>(attp + i);
        lg[i] = l4.x; lg[i + 1] = l4.y; lg[i + 2] = l4.z; lg[i + 3] = l4.w;
    }
#pragma unroll
    for (int i = 0; i < 16; i++) mx = fmaxf(mx, lg[i]);
    float ssum = 0.f;
#pragma unroll
    for (int i = 0; i < 16; i++) { lg[i] = expf(lg[i] - mx); ssum += lg[i]; }
    float sinv = 1.f / ssum;

    float acc0 = 0.f, acc1 = 0.f;

#pragma unroll
    for (int s = 0; s < Ss; s++) {
        int wl = c_wl[s], hl = c_hl[s];
        int base_tok = b * LQ + c_offs[s];
        float fwl = (float)wl, fhl = (float)hl;
#pragma unroll
        for (int k = 0; k < Kk; k++) {
            float w  = lg[s * 4 + k] * sinv;
            float ox = offp[(((h * 4 + s) * 4 + k) * 2) + 0];
            float oy = offp[(((h * 4 + s) * 4 + k) * 2) + 1];
            float x = refx * fwl + ox - 0.5f;
            float y = refy * fhl + oy - 0.5f;
            float x0f = floorf(x), y0f = floorf(y);
            int x0 = (int)x0f, y0 = (int)y0f;
            float wx1 = x - x0f, wx0 = 1.f - wx1;
            float wy1 = y - y0f, wy0 = 1.f - wy1;
#pragma unroll
            for (int c = 0; c < 4; c++) {
                int xi = x0 + (c & 1);
                int yi = y0 + (c >> 1);
                float wc = ((c & 1) ? wx1 : wx0) * ((c >> 1) ? wy1 : wy0);
                bool valid = (xi >= 0) && (xi < wl) && (yi >= 0) && (yi < hl);
                if (valid) {
                    int idx = yi * wl + xi;
                    const __half2* vp = reinterpret_cast<const __half2*>(
                        Vh + ((size_t)(base_tok + idx) * Dm + h * DHh));
                    float ww = w * wc;
                    __half2 hv = __ldg(vp + lane);
                    float2 fv = __half22float2(hv);
                    acc0 = fmaf(ww, fv.x, acc0);
                    acc1 = fmaf(ww, fv.y, acc1);
                }
            }
        }
    }
    size_t base = (size_t)n * Dm + h * DHh;
    __half2 hv; hv.x = __float2half(acc0); hv.y = __float2half(acc1);
    *reinterpret_cast<__half2*>(ACCh + base + 2 * lane) = hv;
}

// ---------------------------------------------------------------------------
// Fused residual-add + LayerNorm, fp16 inputs; fp16 and/or fp32 outputs.
// ---------------------------------------------------------------------------
__global__ void add_layernorm_h_kernel(const __half* __restrict__ A, const __half* __restrict__ Bv,
                                       const float* __restrict__ g, const float* __restrict__ be,
                                       __half* __restrict__ outh, float* __restrict__ outf)
{
    int n = blockIdx.x;
    int t = threadIdx.x;
    float v[4];
    float s = 0.f, ss = 0.f;
    const __half2* a2 = reinterpret_cast<const __half2*>(A + (size_t)n * Dm);
    const __half2* b2 = reinterpret_cast<const __half2*>(Bv + (size_t)n * Dm);
#pragma unroll
    for (int i = 0; i < 2; i++) {
        int d2 = t + i * 128;
        float2 fa = __half22float2(a2[d2]);
        float2 fb = __half22float2(b2[d2]);
        float x0 = fa.x + fb.x, x1 = fa.y + fb.y;
        v[i * 2] = x0; v[i * 2 + 1] = x1;
        s += x0 + x1; ss += x0 * x0 + x1 * x1;
    }
#pragma unroll
    for (int o = 16; o > 0; o >>= 1) {
        s  += __shfl_xor_sync(0xffffffffu, s,  o);
        ss += __shfl_xor_sync(0xffffffffu, ss, o);
    }
    __shared__ float sh[8];
    int w = t >> 5, ln = t & 31;
    if (ln == 0) { sh[w] = s; sh[4 + w] = ss; }
    __syncthreads();
    float ts  = sh[0] + sh[1] + sh[2] + sh[3];
    float tss = sh[4] + sh[5] + sh[6] + sh[7];
    float mu  = ts * (1.f / Dm);
    float var = tss * (1.f / Dm) - mu * mu;
    float inv = rsqrtf(var + 1e-5f);
#pragma unroll
    for (int i = 0; i < 2; i++) {
        int d2 = t + i * 128;
        int d = d2 * 2;
        float o0 = (v[i * 2]     - mu) * inv * g[d]     + be[d];
        float o1 = (v[i * 2 + 1] - mu) * inv * g[d + 1] + be[d + 1];
        if (outh) {
            __half2 hv; hv.x = __float2half(o0); hv.y = __float2half(o1);
            *reinterpret_cast<__half2*>(outh + (size_t)n * Dm + d) = hv;
        }
        if (outf) {
            *reinterpret_cast<float2*>(outf + (size_t)n * Dm + d) = make_float2(o0, o1);
        }
    }
}

// ---------------------------------------------------------------------------
// Launch
// ---------------------------------------------------------------------------
extern "C" void kernel_launch(void* const* d_in, const int* in_sizes, int n_in,
                              void* d_out, int out_size)
{
    const float* srcs[4] = {nullptr, nullptr, nullptr, nullptr};
    const float* refs[4] = {nullptr, nullptr, nullptr, nullptr};
    const int src_sz[4] = {Bb * 56 * 56 * Dm, Bb * 28 * 28 * Dm, Bb * 14 * 14 * Dm, Bb * 7 * 7 * Dm};
    const int ref_sz[4] = {Bb * 56 * 56 * 2,  Bb * 28 * 28 * 2,  Bb * 14 * 14 * 2,  Bb * 7 * 7 * 2};
    for (int i = 0; i < 8; i++) {
        int sz = in_sizes[i];
        for (int l = 0; l < 4; l++) {
            if (sz == src_sz[l] && !srcs[l]) { srcs[l] = (const float*)d_in[i]; goto next; }
        }
        for (int l = 0; l < 4; l++) {
            if (sz == ref_sz[l] && !refs[l]) { refs[l] = (const float*)d_in[i]; goto next; }
        }
    next:;
    }

    const float* Wv    = (const float*)d_in[8];
    const float* bv    = (const float*)d_in[9];
    const float* Woff  = (const float*)d_in[10];
    const float* boff  = (const float*)d_in[11];
    const float* Wattn = (const float*)d_in[12];
    const float* battn = (const float*)d_in[13];
    const float* Wo    = (const float*)d_in[14];
    const float* bo    = (const float*)d_in[15];
    const float* W1    = (const float*)d_in[16];
    const float* b1    = (const float*)d_in[17];
    const float* W2    = (const float*)d_in[18];
    const float* b2    = (const float*)d_in[19];
    const float* g1    = (const float*)d_in[20];
    const float* be1   = (const float*)d_in[21];
    const float* g2    = (const float*)d_in[22];
    const float* be2   = (const float*)d_in[23];
    float* out = (float*)d_out;

    float *REF, *OA, *ball;
    __half *Qh, *Vh, *ACCh, *A2h, *Xh, *Hbh, *Yh, *Wah, *Woh, *W1h, *W2h;
    cudaGetSymbolAddress((void**)&REF,  g_REF);
    cudaGetSymbolAddress((void**)&OA,   g_OA);
    cudaGetSymbolAddress((void**)&ball, g_ball);
    cudaGetSymbolAddress((void**)&Qh,   g_Qh);
    cudaGetSymbolAddress((void**)&Vh,   g_Vh);
    cudaGetSymbolAddress((void**)&ACCh, g_ACCh);
    cudaGetSymbolAddress((void**)&A2h,  g_A2h);
    cudaGetSymbolAddress((void**)&Xh,   g_Xh);
    cudaGetSymbolAddress((void**)&Hbh,  g_Hbh);
    cudaGetSymbolAddress((void**)&Yh,   g_Yh);
    cudaGetSymbolAddress((void**)&Wah,  g_Wah);
    cudaGetSymbolAddress((void**)&Woh,  g_Woh);
    cudaGetSymbolAddress((void**)&W1h,  g_W1h);
    cudaGetSymbolAddress((void**)&W2h,  g_W2h);

    cudaFuncSetAttribute(gemm_fp16_kernel<0>, cudaFuncAttributeMaxDynamicSharedMemorySize, SMEM_GEMM);
    cudaFuncSetAttribute(gemm_fp16_kernel<1>, cudaFuncAttributeMaxDynamicSharedMemorySize, SMEM_GEMM);
    cudaFuncSetAttribute(gemm_fp16_kernel<2>, cudaFuncAttributeMaxDynamicSharedMemorySize, SMEM_GEMM);
    cudaFuncSetAttribute(gemm_fp16_kernel<3>, cudaFuncAttributeMaxDynamicSharedMemorySize, SMEM_GEMM);

    const int rowBlocks = (NTOK + 127) / 128;   // 131
    dim3 blk(256);

    // 0: merged VOA weight
    merge_h_kernel<<<(Dm * MVOA + 255) / 256, 256>>>(Wv, Woff, Wattn, bv, boff, battn, Wah, ball);
    // 1: all other weight converts (one kernel)
    {
        int total = N_W1 + N_W2 + N_WO;
        conv_all_kernel<<<(total + 255) / 256, 256>>>(W1, W2, Wo, W1h, W2h, Woh);
    }
    // 2: pack (Q + REF folded)
    {
        int total = NTOK * (Dm / 4);
        pack_kernel<<<(total + 255) / 256, 256>>>(srcs[0], srcs[1], srcs[2], srcs[3],
                                                  refs[0], refs[1], refs[2], refs[3], Qh, REF);
    }
    // 3: [Vh | OA] = Q @ [Wv|Woff|Wattn] + bias
    gemm_fp16_kernel<2><<<dim3(MVOA / 64, rowBlocks), blk, SMEM_GEMM>>>(Qh, Wah, ball, Vh, OA, NTOK, Dm, MVOA);
    // 4: sampling (fused softmax) -> ACCh
    {
        int warps = NTOK * Hh;
        sample_kernel<<<(warps + 7) / 8, 256>>>(Vh, OA, REF, ACCh);
    }
    // 5: A2h = ACC @ Wo + bo  (fp16 out)
    gemm_fp16_kernel<3><<<dim3(Dm / 64, rowBlocks), blk, SMEM_GEMM>>>(ACCh, Woh, bo, A2h, nullptr, NTOK, Dm, Dm);
    // 6: Xh = LN(Qh + A2h)
    add_layernorm_h_kernel<<<NTOK, 128>>>(Qh, A2h, g1, be1, Xh, nullptr);
    // 7: Hbh = fp16(relu(X @ W1 + b1))
    gemm_fp16_kernel<1><<<dim3(DFFm / 64, rowBlocks), blk, SMEM_GEMM>>>(Xh, W1h, b1, Hbh, nullptr, NTOK, Dm, DFFm);
    // 8: Yh = Hb @ W2 + b2  (fp16 out)
    gemm_fp16_kernel<3><<<dim3(Dm / 64, rowBlocks), blk, SMEM_GEMM>>>(Hbh, W2h, b2, Yh, nullptr, NTOK, DFFm, Dm);
    // 9: out = LN(Xh + Yh)  (fp32 to d_out)
    add_layernorm_h_kernel<<<NTOK, 128>>>(Xh, Yh, g2, be2, nullptr, out);
}

// round 14
// speedup vs baseline: 1.1259x; 1.0948x over previous
#include <cuda_runtime.h>
#include <cuda_fp16.h>
#include <cstdint>

// ---------------------------------------------------------------------------
// Problem constants
// ---------------------------------------------------------------------------
#define Dm    512
#define Hh    8
#define DHh   64
#define DFFm  2048
#define Kk    4
#define Ss    4
#define Bb    4
#define LQ    4165
#define NTOK  (Bb * LQ)     // 16660
#define MVOA  896           // merged V(512) + OFF(256) + ATT(128)
#define MOA2  384           // OFF+ATT width

__device__ __constant__ int c_wl[4]   = {56, 28, 14, 7};
__device__ __constant__ int c_hl[4]   = {56, 28, 14, 7};
__device__ __constant__ int c_offs[4] = {0, 3136, 3920, 4116};

// ---------------------------------------------------------------------------
// Scratch
// ---------------------------------------------------------------------------
__device__ float g_REF [(size_t)NTOK * 2];
__device__ float g_OA  [(size_t)NTOK * MOA2];   // OFF | ATT logits (fp32)
__device__ float g_ball[MVOA];

// fp16 buffers
__device__ __half g_Qh  [(size_t)NTOK * Dm];
__device__ __half g_Vh  [(size_t)NTOK * Dm];
__device__ __half g_ACCh[(size_t)NTOK * Dm];
__device__ __half g_A2h [(size_t)NTOK * Dm];
__device__ __half g_Xh  [(size_t)NTOK * Dm];
__device__ __half g_Hbh [(size_t)NTOK * DFFm];
__device__ __half g_Yh  [(size_t)NTOK * Dm];
__device__ __half g_Wah [(size_t)Dm * MVOA];
__device__ __half g_Woh [(size_t)Dm * Dm];
__device__ __half g_W1h [(size_t)Dm * DFFm];
__device__ __half g_W2h [(size_t)DFFm * Dm];

// ---------------------------------------------------------------------------
__device__ __forceinline__ int scale_of(int p, int& loc) {
    if (p < 3136)      { loc = p;        return 0; }
    else if (p < 3920) { loc = p - 3136; return 1; }
    else if (p < 4116) { loc = p - 3920; return 2; }
    else               { loc = p - 4116; return 3; }
}

// ---------------------------------------------------------------------------
// pack: srcs -> Qh fp16; refs -> REF (folded)
// ---------------------------------------------------------------------------
__global__ void pack_kernel(const float* __restrict__ s0, const float* __restrict__ s1,
                            const float* __restrict__ s2, const float* __restrict__ s3,
                            const float* __restrict__ r0, const float* __restrict__ r1,
                            const float* __restrict__ r2, const float* __restrict__ r3,
                            __half* __restrict__ Qh, float* __restrict__ REF)
{
    int e = blockIdx.x * blockDim.x + threadIdx.x;
    const int total = NTOK * (Dm / 4);
    if (e >= total) return;
    int n  = e >> 7;
    int d4 = e & 127;
    int b = n / LQ;
    int p = n % LQ;
    int loc;
    int l = scale_of(p, loc);
    const float* src = (l == 0) ? s0 : (l == 1) ? s1 : (l == 2) ? s2 : s3;
    int lq = c_wl[l] * c_hl[l];
    float4 v = reinterpret_cast<const float4*>(src)[(size_t)(b * lq + loc) * 128 + d4];
    __half h[4] = {__float2half(v.x), __float2half(v.y), __float2half(v.z), __float2half(v.w)};
    *reinterpret_cast<uint2*>(Qh + (size_t)n * Dm + d4 * 4) = *reinterpret_cast<uint2*>(h);

    if (e < NTOK) {
        int nb = e / LQ, pp = e % LQ, lc;
        int ll = scale_of(pp, lc);
        const float* rsrc = (ll == 0) ? r0 : (ll == 1) ? r1 : (ll == 2) ? r2 : r3;
        int lq2 = c_wl[ll] * c_hl[ll];
        float2 rv = *reinterpret_cast<const float2*>(rsrc + (size_t)(nb * lq2 + lc) * 2);
        *reinterpret_cast<float2*>(REF + (size_t)e * 2) = rv;
    }
}

// ---------------------------------------------------------------------------
// ONE prep kernel: merged VOA weight+bias and W1/W2/Wo fp16 converts.
// index space: [0, Dm*MVOA) -> Wah ; then W1 ; then W2 ; then Wo ; bias tail.
// ---------------------------------------------------------------------------
#define N_WA (Dm * MVOA)
#define N_W1 (Dm * DFFm)
#define N_W2 (DFFm * Dm)
#define N_WO (Dm * Dm)
__global__ void prep_w_kernel(const float* __restrict__ Wv, const float* __restrict__ Woff,
                              const float* __restrict__ Wattn,
                              const float* __restrict__ bv, const float* __restrict__ boff,
                              const float* __restrict__ battn,
                              const float* __restrict__ W1, const float* __restrict__ W2,
                              const float* __restrict__ Wo,
                              __half* __restrict__ Wah, float* __restrict__ ball,
                              __half* __restrict__ W1h, __half* __restrict__ W2h,
                              __half* __restrict__ Woh)
{
    int i = blockIdx.x * blockDim.x + threadIdx.x;
    if (i < N_WA) {
        int r = i / MVOA, c = i % MVOA;
        float w;
        if (c < 512)       w = Wv[r * 512 + c];
        else if (c < 768)  w = Woff[r * 256 + (c - 512)];
        else               w = Wattn[r * 128 + (c - 768)];
        Wah[i] = __float2half(w);
    } else if (i < N_WA + N_W1) {
        int j = i - N_WA;
        W1h[j] = __float2half(W1[j]);
    } else if (i < N_WA + N_W1 + N_W2) {
        int j = i - N_WA - N_W1;
        W2h[j] = __float2half(W2[j]);
    } else if (i < N_WA + N_W1 + N_W2 + N_WO) {
        int j = i - N_WA - N_W1 - N_W2;
        Woh[j] = __float2half(Wo[j]);
    }
    if (i < MVOA)
        ball[i] = (i < 512) ? bv[i] : (i < 768) ? boff[i - 512] : battn[i - 768];
}

// ---------------------------------------------------------------------------
// fp16 GEMM via mma.sync.m16n8k16, 128x128 tile, BK=32, 4-stage cp.async.
// (exact R10 configuration — empirically fastest of the three tried)
// MODE 0: fp32 out. MODE 1: relu->fp16. MODE 3: fp16.
// MODE 2: colBase<512 -> fp16 Vh; else fp32 OA.
// ---------------------------------------------------------------------------
#define LDSM4(r, addr) \
    asm volatile("ldmatrix.sync.aligned.m8n8.x4.shared.b16 {%0,%1,%2,%3}, [%4];" \
                 : "=r"((r)[0]), "=r"((r)[1]), "=r"((r)[2]), "=r"((r)[3]) : "r"(addr))
#define LDSM4T(r, addr) \
    asm volatile("ldmatrix.sync.aligned.m8n8.x4.trans.shared.b16 {%0,%1,%2,%3}, [%4];" \
                 : "=r"((r)[0]), "=r"((r)[1]), "=r"((r)[2]), "=r"((r)[3]) : "r"(addr))
#define MMA16816H(c, a, b) \
    asm volatile("mma.sync.aligned.m16n8k16.row.col.f32.f16.f16.f32 " \
                 "{%0,%1,%2,%3}, {%4,%5,%6,%7}, {%8,%9}, {%0,%1,%2,%3};" \
                 : "+f"((c)[0]), "+f"((c)[1]), "+f"((c)[2]), "+f"((c)[3]) \
                 : "r"((a)[0]), "r"((a)[1]), "r"((a)[2]), "r"((a)[3]), \
                   "r"((b)[0]), "r"((b)[1]))

#define STAGE_BYTES 18944            // 10240 (A: 128x32 @80B) + 8704 (B: 32x128 @272B)
#define SMEM_GEMM   (4 * STAGE_BYTES)

template<int MODE>
__global__ __launch_bounds__(256, 2)
void gemm_fp16_kernel(const __half* __restrict__ A,
                      const __half* __restrict__ W,
                      const float* __restrict__ bias, void* __restrict__ Cout,
                      void* __restrict__ Cout2,
                      int N, int K, int M)
{
    extern __shared__ char smem[];
    const uint32_t sdata = (uint32_t)__cvta_generic_to_shared(smem);

    const int tid  = threadIdx.x;
    const int lane = tid & 31;
    const int wid  = tid >> 5;
    const int wm = (wid & 1) * 64;
    const int wn = (wid >> 1) * 32;
    const int rowBase = blockIdx.y * 128;
    const int colBase = blockIdx.x * 128;

    const int lrowA = lane & 15;
    const int lcolA = (lane >> 4) * 8;
    const uint32_t aFragOff = (uint32_t)((wm + lrowA) * 80 + lcolA * 2);
    const int grp = lane >> 3;
    const int rB  = lane & 7;
    const uint32_t bFragOff = (uint32_t)(10240 + ((grp & 1) * 8 + rB) * 272 + (grp >> 1) * 16 + wn * 2);

    const int T = K >> 5;

    float acc[4][4][4];
#pragma unroll
    for (int i = 0; i < 4; i++)
#pragma unroll
        for (int j = 0; j < 4; j++)
#pragma unroll
            for (int r = 0; r < 4; r++) acc[i][j][r] = 0.f;

    auto loadStage = [&](int t, int stage) {
        int kp0 = t << 5;
        uint32_t sb = sdata + stage * STAGE_BYTES;
#pragma unroll
        for (int i = 0; i < 2; i++) {
            int id = tid * 2 + i;
            int r = id >> 2, c = id & 3;
            int gr = rowBase + r;
            const void* src = (const void*)(A + (size_t)gr * K + kp0 + c * 8);
            uint32_t dst = sb + r * 80 + c * 16;
            int sz = (gr < N) ? 16 : 0;
            asm volatile("cp.async.cg.shared.global [%0], [%1], 16, %2;"
                         :: "r"(dst), "l"(src), "r"(sz));
        }
#pragma unroll
        for (int i = 0; i < 2; i++) {
            int id = tid * 2 + i;
            int r = id >> 4, c = id & 15;
            const void* src = (const void*)(W + (size_t)(kp0 + r) * M + colBase + c * 8);
            uint32_t dst = sb + 10240 + r * 272 + c * 16;
            asm volatile("cp.async.cg.shared.global [%0], [%1], 16;"
                         :: "r"(dst), "l"(src));
        }
        asm volatile("cp.async.commit_group;" ::: "memory");
    };

    loadStage(0, 0);
    if (T > 1) loadStage(1, 1);
    if (T > 2) loadStage(2, 2);

    for (int t = 0; t < T; t++) {
        int rem = T - 1 - t;
        if (rem >= 2)      asm volatile("cp.async.wait_group 2;" ::: "memory");
        else if (rem == 1) asm volatile("cp.async.wait_group 1;" ::: "memory");
        else               asm volatile("cp.async.wait_group 0;" ::: "memory");
        __syncthreads();

        if (t + 3 < T) loadStage(t + 3, (t + 3) & 3);

        uint32_t sb = sdata + (t & 3) * STAGE_BYTES;
        uint32_t aBase = sb + aFragOff;
        uint32_t bBase = sb + bFragOff;
#pragma unroll
        for (int ks = 0; ks < 2; ks++) {
            uint32_t af[4][4];
            uint32_t bfr[4][2];
            uint32_t aB = aBase + ks * 32;
            uint32_t bB = bBase + ks * 4352;
#pragma unroll
            for (int mt = 0; mt < 4; mt++) LDSM4(af[mt], aB + mt * 1280);
#pragma unroll
            for (int np = 0; np < 2; np++) {
                uint32_t r4[4];
                LDSM4T(r4, bB + np * 32);
                bfr[np * 2][0] = r4[0]; bfr[np * 2][1] = r4[1];
                bfr[np * 2 + 1][0] = r4[2]; bfr[np * 2 + 1][1] = r4[3];
            }
#pragma unroll
            for (int mt = 0; mt < 4; mt++)
#pragma unroll
                for (int nt = 0; nt < 4; nt++)
                    MMA16816H(acc[mt][nt], af[mt], bfr[nt]);
        }
    }

    // epilogue
    const int mr = lane >> 2;
    const int nc = (lane & 3) * 2;
    const bool vpart = (MODE == 2) && (colBase < 512);

#pragma unroll
    for (int mt = 0; mt < 4; mt++) {
#pragma unroll
        for (int nt = 0; nt < 4; nt++) {
            int n0 = colBase + wn + nt * 8 + nc;
            float bb0 = bias[n0], bb1 = bias[n0 + 1];
#pragma unroll
            for (int half = 0; half < 2; half++) {
                int m = rowBase + wm + mt * 16 + mr + half * 8;
                if (m >= N) continue;
                float v0 = acc[mt][nt][half * 2 + 0] + bb0;
                float v1 = acc[mt][nt][half * 2 + 1] + bb1;
                if (MODE == 0) {
                    *reinterpret_cast<float2*>((float*)Cout + (size_t)m * M + n0) = make_float2(v0, v1);
                } else if (MODE == 1 || MODE == 3) {
                    if (MODE == 1) { v0 = fmaxf(v0, 0.f); v1 = fmaxf(v1, 0.f); }
                    __half2 hv; hv.x = __float2half(v0); hv.y = __float2half(v1);
                    *reinterpret_cast<__half2*>((__half*)Cout + (size_t)m * M + n0) = hv;
                } else {
                    if (vpart) {
                        __half2 hv; hv.x = __float2half(v0); hv.y = __float2half(v1);
                        *reinterpret_cast<__half2*>((__half*)Cout + (size_t)m * Dm + n0) = hv;
                    } else {
                        *reinterpret_cast<float2*>((float*)Cout2 + (size_t)m * MOA2 + (n0 - 512)) = make_float2(v0, v1);
                    }
                }
            }
        }
    }
}

// ---------------------------------------------------------------------------
// Deformable sampling with fused softmax (branchy gathers, __expf).
// ---------------------------------------------------------------------------
__global__ void sample_kernel(const __half* __restrict__ Vh, const float* __restrict__ OA,
                              const float* __restrict__ REF, __half* __restrict__ ACCh)
{
    int wid = blockIdx.x * (blockDim.x / 32) + (threadIdx.x / 32);
    if (wid >= NTOK * Hh) return;
    int lane = threadIdx.x & 31;
    int n = wid / Hh;
    int h = wid % Hh;
    int b = n / LQ;

    float refx = REF[(size_t)n * 2 + 0];
    float refy = REF[(size_t)n * 2 + 1];
    const float* offp = OA + (size_t)n * MOA2;
    const float* attp = OA + (size_t)n * MOA2 + 256 + h * 16;

    float lg[16], mx = -1e30f;
#pragma unroll
    for (int i = 0; i < 16; i += 4) {
        float4 l4 = *reinterpret_cast<const float4*>(attp + i);
        lg[i] = l4.x; lg[i + 1] = l4.y; lg[i + 2] = l4.z; lg[i + 3] = l4.w;
    }
#pragma unroll
    for (int i = 0; i < 16; i++) mx = fmaxf(mx, lg[i]);
    float ssum = 0.f;
#pragma unroll
    for (int i = 0; i < 16; i++) { lg[i] = __expf(lg[i] - mx); ssum += lg[i]; }
    float sinv = 1.f / ssum;

    float acc0 = 0.f, acc1 = 0.f;

#pragma unroll
    for (int s = 0; s < Ss; s++) {
        int wl = c_wl[s], hl = c_hl[s];
        int base_tok = b * LQ + c_offs[s];
        float fwl = (float)wl, fhl = (float)hl;
#pragma unroll
        for (int k = 0; k < Kk; k++) {
            float w  = lg[s * 4 + k] * sinv;
            float ox = offp[(((h * 4 + s) * 4 + k) * 2) + 0];
            float oy = offp[(((h * 4 + s) * 4 + k) * 2) + 1];
            float x = refx * fwl + ox - 0.5f;
            float y = refy * fhl + oy - 0.5f;
            float x0f = floorf(x), y0f = floorf(y);
            int x0 = (int)x0f, y0 = (int)y0f;
            float wx1 = x - x0f, wx0 = 1.f - wx1;
            float wy1 = y - y0f, wy0 = 1.f - wy1;
#pragma unroll
            for (int c = 0; c < 4; c++) {
                int xi = x0 + (c & 1);
                int yi = y0 + (c >> 1);
                float wc = ((c & 1) ? wx1 : wx0) * ((c >> 1) ? wy1 : wy0);
                bool valid = (xi >= 0) && (xi < wl) && (yi >= 0) && (yi < hl);
                if (valid) {
                    int idx = yi * wl + xi;
                    const __half2* vp = reinterpret_cast<const __half2*>(
                        Vh + ((size_t)(base_tok + idx) * Dm + h * DHh));
                    float ww = w * wc;
                    __half2 hv = __ldg(vp + lane);
                    float2 fv = __half22float2(hv);
                    acc0 = fmaf(ww, fv.x, acc0);
                    acc1 = fmaf(ww, fv.y, acc1);
                }
            }
        }
    }
    size_t base = (size_t)n * Dm + h * DHh;
    __half2 hv; hv.x = __float2half(acc0); hv.y = __float2half(acc1);
    *reinterpret_cast<__half2*>(ACCh + base + 2 * lane) = hv;
}

// ---------------------------------------------------------------------------
// Fused residual-add + LayerNorm, fp16 inputs; fp16 and/or fp32 outputs.
// ---------------------------------------------------------------------------
__global__ void add_layernorm_h_kernel(const __half* __restrict__ A, const __half* __restrict__ Bv,
                                       const float* __restrict__ g, const float* __restrict__ be,
                                       __half* __restrict__ outh, float* __restrict__ outf)
{
    int n = blockIdx.x;
    int t = threadIdx.x;
    float v[4];
    float s = 0.f, ss = 0.f;
    const __half2* a2 = reinterpret_cast<const __half2*>(A + (size_t)n * Dm);
    const __half2* b2 = reinterpret_cast<const __half2*>(Bv + (size_t)n * Dm);
#pragma unroll
    for (int i = 0; i < 2; i++) {
        int d2 = t + i * 128;
        float2 fa = __half22float2(a2[d2]);
        float2 fb = __half22float2(b2[d2]);
        float x0 = fa.x + fb.x, x1 = fa.y + fb.y;
        v[i * 2] = x0; v[i * 2 + 1] = x1;
        s += x0 + x1; ss += x0 * x0 + x1 * x1;
    }
#pragma unroll
    for (int o = 16; o > 0; o >>= 1) {
        s  += __shfl_xor_sync(0xffffffffu, s,  o);
        ss += __shfl_xor_sync(0xffffffffu, ss, o);
    }
    __shared__ float sh[8];
    int w = t >> 5, ln = t & 31;
    if (ln == 0) { sh[w] = s; sh[4 + w] = ss; }
    __syncthreads();
    float ts  = sh[0] + sh[1] + sh[2] + sh[3];
    float tss = sh[4] + sh[5] + sh[6] + sh[7];
    float mu  = ts * (1.f / Dm);
    float var = tss * (1.f / Dm) - mu * mu;
    float inv = rsqrtf(var + 1e-5f);
#pragma unroll
    for (int i = 0; i < 2; i++) {
        int d2 = t + i * 128;
        int d = d2 * 2;
        float o0 = (v[i * 2]     - mu) * inv * g[d]     + be[d];
        float o1 = (v[i * 2 + 1] - mu) * inv * g[d + 1] + be[d + 1];
        if (outh) {
            __half2 hv; hv.x = __float2half(o0); hv.y = __float2half(o1);
            *reinterpret_cast<__half2*>(outh + (size_t)n * Dm + d) = hv;
        }
        if (outf) {
            *reinterpret_cast<float2*>(outf + (size_t)n * Dm + d) = make_float2(o0, o1);
        }
    }
}

// ---------------------------------------------------------------------------
// Launch
// ---------------------------------------------------------------------------
extern "C" void kernel_launch(void* const* d_in, const int* in_sizes, int n_in,
                              void* d_out, int out_size)
{
    const float* srcs[4] = {nullptr, nullptr, nullptr, nullptr};
    const float* refs[4] = {nullptr, nullptr, nullptr, nullptr};
    const int src_sz[4] = {Bb * 56 * 56 * Dm, Bb * 28 * 28 * Dm, Bb * 14 * 14 * Dm, Bb * 7 * 7 * Dm};
    const int ref_sz[4] = {Bb * 56 * 56 * 2,  Bb * 28 * 28 * 2,  Bb * 14 * 14 * 2,  Bb * 7 * 7 * 2};
    for (int i = 0; i < 8; i++) {
        int sz = in_sizes[i];
        for (int l = 0; l < 4; l++) {
            if (sz == src_sz[l] && !srcs[l]) { srcs[l] = (const float*)d_in[i]; goto next; }
        }
        for (int l = 0; l < 4; l++) {
            if (sz == ref_sz[l] && !refs[l]) { refs[l] = (const float*)d_in[i]; goto next; }
        }
    next:;
    }

    const float* Wv    = (const float*)d_in[8];
    const float* bv    = (const float*)d_in[9];
    const float* Woff  = (const float*)d_in[10];
    const float* boff  = (const float*)d_in[11];
    const float* Wattn = (const float*)d_in[12];
    const float* battn = (const float*)d_in[13];
    const float* Wo    = (const float*)d_in[14];
    const float* bo    = (const float*)d_in[15];
    const float* W1    = (const float*)d_in[16];
    const float* b1    = (const float*)d_in[17];
    const float* W2    = (const float*)d_in[18];
    const float* b2    = (const float*)d_in[19];
    const float* g1    = (const float*)d_in[20];
    const float* be1   = (const float*)d_in[21];
    const float* g2    = (const float*)d_in[22];
    const float* be2   = (const float*)d_in[23];
    float* out = (float*)d_out;

    float *REF, *OA, *ball;
    __half *Qh, *Vh, *ACCh, *A2h, *Xh, *Hbh, *Yh, *Wah, *Woh, *W1h, *W2h;
    cudaGetSymbolAddress((void**)&REF,  g_REF);
    cudaGetSymbolAddress((void**)&OA,   g_OA);
    cudaGetSymbolAddress((void**)&ball, g_ball);
    cudaGetSymbolAddress((void**)&Qh,   g_Qh);
    cudaGetSymbolAddress((void**)&Vh,   g_Vh);
    cudaGetSymbolAddress((void**)&ACCh, g_ACCh);
    cudaGetSymbolAddress((void**)&A2h,  g_A2h);
    cudaGetSymbolAddress((void**)&Xh,   g_Xh);
    cudaGetSymbolAddress((void**)&Hbh,  g_Hbh);
    cudaGetSymbolAddress((void**)&Yh,   g_Yh);
    cudaGetSymbolAddress((void**)&Wah,  g_Wah);
    cudaGetSymbolAddress((void**)&Woh,  g_Woh);
    cudaGetSymbolAddress((void**)&W1h,  g_W1h);
    cudaGetSymbolAddress((void**)&W2h,  g_W2h);

    cudaFuncSetAttribute(gemm_fp16_kernel<0>, cudaFuncAttributeMaxDynamicSharedMemorySize, SMEM_GEMM);
    cudaFuncSetAttribute(gemm_fp16_kernel<1>, cudaFuncAttributeMaxDynamicSharedMemorySize, SMEM_GEMM);
    cudaFuncSetAttribute(gemm_fp16_kernel<2>, cudaFuncAttributeMaxDynamicSharedMemorySize, SMEM_GEMM);
    cudaFuncSetAttribute(gemm_fp16_kernel<3>, cudaFuncAttributeMaxDynamicSharedMemorySize, SMEM_GEMM);

    const int rowBlocks = (NTOK + 127) / 128;   // 131
    dim3 blk(256);

    // 0: ALL weight prep in one kernel
    {
        int total = N_WA + N_W1 + N_W2 + N_WO;
        prep_w_kernel<<<(total + 255) / 256, 256>>>(Wv, Woff, Wattn, bv, boff, battn,
                                                    W1, W2, Wo, Wah, ball, W1h, W2h, Woh);
    }
    // 1: pack (Q + REF folded)
    {
        int total = NTOK * (Dm / 4);
        pack_kernel<<<(total + 255) / 256, 256>>>(srcs[0], srcs[1], srcs[2], srcs[3],
                                                  refs[0], refs[1], refs[2], refs[3], Qh, REF);
    }
    // 2: [Vh | OA] = Q @ [Wv|Woff|Wattn] + bias
    gemm_fp16_kernel<2><<<dim3(MVOA / 128, rowBlocks), blk, SMEM_GEMM>>>(Qh, Wah, ball, Vh, OA, NTOK, Dm, MVOA);
    // 3: sampling (fused softmax) -> ACCh
    {
        int warps = NTOK * Hh;
        sample_kernel<<<(warps + 7) / 8, 256>>>(Vh, OA, REF, ACCh);
    }
    // 4: A2h = ACC @ Wo + bo  (fp16 out)
    gemm_fp16_kernel<3><<<dim3(Dm / 128, rowBlocks), blk, SMEM_GEMM>>>(ACCh, Woh, bo, A2h, nullptr, NTOK, Dm, Dm);
    // 5: Xh = LN(Qh + A2h)
    add_layernorm_h_kernel<<<NTOK, 128>>>(Qh, A2h, g1, be1, Xh, nullptr);
    // 6: Hbh = fp16(relu(X @ W1 + b1))
    gemm_fp16_kernel<1><<<dim3(DFFm / 128, rowBlocks), blk, SMEM_GEMM>>>(Xh, W1h, b1, Hbh, nullptr, NTOK, Dm, DFFm);
    // 7: Yh = Hb @ W2 + b2  (fp16 out)
    gemm_fp16_kernel<3><<<dim3(Dm / 128, rowBlocks), blk, SMEM_GEMM>>>(Hbh, W2h, b2, Yh, nullptr, NTOK, DFFm, Dm);
    // 8: out = LN(Xh + Yh)  (fp32 to d_out)
    add_layernorm_h_kernel<<<NTOK, 128>>>(Xh, Yh, g2, be2, nullptr, out);
}

// round 15
// speedup vs baseline: 1.3848x; 1.2299x over previous
#include <cuda_runtime.h>
#include <cuda_fp16.h>
#include <cstdint>

// ---------------------------------------------------------------------------
// Problem constants
// ---------------------------------------------------------------------------
#define Dm    512
#define Hh    8
#define DHh   64
#define DFFm  2048
#define Kk    4
#define Ss    4
#define Bb    4
#define LQ    4165
#define NTOK  (Bb * LQ)     // 16660
#define MVOA  896           // merged V(512) + OFF(256) + ATT(128)
#define MOA2  384           // OFF+ATT width

__device__ __constant__ int c_wl[4]   = {56, 28, 14, 7};
__device__ __constant__ int c_hl[4]   = {56, 28, 14, 7};
__device__ __constant__ int c_offs[4] = {0, 3136, 3920, 4116};

// ---------------------------------------------------------------------------
// Scratch
// ---------------------------------------------------------------------------
__device__ float g_REF [(size_t)NTOK * 2];
__device__ float g_OA  [(size_t)NTOK * MOA2];   // OFF | ATT logits (fp32)
__device__ float g_ball[MVOA];

// fp16 buffers
__device__ __half g_Qh  [(size_t)NTOK * Dm];
__device__ __half g_Vh  [(size_t)NTOK * Dm];
__device__ __half g_ACCh[(size_t)NTOK * Dm];
__device__ __half g_A2h [(size_t)NTOK * Dm];
__device__ __half g_Xh  [(size_t)NTOK * Dm];
__device__ __half g_Hbh [(size_t)NTOK * DFFm];
__device__ __half g_Yh  [(size_t)NTOK * Dm];
__device__ __half g_Wah [(size_t)Dm * MVOA];
__device__ __half g_Woh [(size_t)Dm * Dm];
__device__ __half g_W1h [(size_t)Dm * DFFm];
__device__ __half g_W2h [(size_t)DFFm * Dm];

// ---------------------------------------------------------------------------
__device__ __forceinline__ int scale_of(int p, int& loc) {
    if (p < 3136)      { loc = p;        return 0; }
    else if (p < 3920) { loc = p - 3136; return 1; }
    else if (p < 4116) { loc = p - 3920; return 2; }
    else               { loc = p - 4116; return 3; }
}

// ---------------------------------------------------------------------------
// pack: srcs -> Qh fp16; refs -> REF (folded)
// ---------------------------------------------------------------------------
__global__ void pack_kernel(const float* __restrict__ s0, const float* __restrict__ s1,
                            const float* __restrict__ s2, const float* __restrict__ s3,
                            const float* __restrict__ r0, const float* __restrict__ r1,
                            const float* __restrict__ r2, const float* __restrict__ r3,
                            __half* __restrict__ Qh, float* __restrict__ REF)
{
    int e = blockIdx.x * blockDim.x + threadIdx.x;
    const int total = NTOK * (Dm / 4);
    if (e >= total) return;
    int n  = e >> 7;
    int d4 = e & 127;
    int b = n / LQ;
    int p = n % LQ;
    int loc;
    int l = scale_of(p, loc);
    const float* src = (l == 0) ? s0 : (l == 1) ? s1 : (l == 2) ? s2 : s3;
    int lq = c_wl[l] * c_hl[l];
    float4 v = reinterpret_cast<const float4*>(src)[(size_t)(b * lq + loc) * 128 + d4];
    __half h[4] = {__float2half(v.x), __float2half(v.y), __float2half(v.z), __float2half(v.w)};
    *reinterpret_cast<uint2*>(Qh + (size_t)n * Dm + d4 * 4) = *reinterpret_cast<uint2*>(h);

    if (e < NTOK) {
        int nb = e / LQ, pp = e % LQ, lc;
        int ll = scale_of(pp, lc);
        const float* rsrc = (ll == 0) ? r0 : (ll == 1) ? r1 : (ll == 2) ? r2 : r3;
        int lq2 = c_wl[ll] * c_hl[ll];
        float2 rv = *reinterpret_cast<const float2*>(rsrc + (size_t)(nb * lq2 + lc) * 2);
        *reinterpret_cast<float2*>(REF + (size_t)e * 2) = rv;
    }
}

// ---------------------------------------------------------------------------
// ONE prep kernel: merged VOA weight+bias and W1/W2/Wo fp16 converts.
// ---------------------------------------------------------------------------
#define N_WA (Dm * MVOA)
#define N_W1 (Dm * DFFm)
#define N_W2 (DFFm * Dm)
#define N_WO (Dm * Dm)
__global__ void prep_w_kernel(const float* __restrict__ Wv, const float* __restrict__ Woff,
                              const float* __restrict__ Wattn,
                              const float* __restrict__ bv, const float* __restrict__ boff,
                              const float* __restrict__ battn,
                              const float* __restrict__ W1, const float* __restrict__ W2,
                              const float* __restrict__ Wo,
                              __half* __restrict__ Wah, float* __restrict__ ball,
                              __half* __restrict__ W1h, __half* __restrict__ W2h,
                              __half* __restrict__ Woh)
{
    int i = blockIdx.x * blockDim.x + threadIdx.x;
    if (i < N_WA) {
        int r = i / MVOA, c = i % MVOA;
        float w;
        if (c < 512)       w = Wv[r * 512 + c];
        else if (c < 768)  w = Woff[r * 256 + (c - 512)];
        else               w = Wattn[r * 128 + (c - 768)];
        Wah[i] = __float2half(w);
    } else if (i < N_WA + N_W1) {
        int j = i - N_WA;
        W1h[j] = __float2half(W1[j]);
    } else if (i < N_WA + N_W1 + N_W2) {
        int j = i - N_WA - N_W1;
        W2h[j] = __float2half(W2[j]);
    } else if (i < N_WA + N_W1 + N_W2 + N_WO) {
        int j = i - N_WA - N_W1 - N_W2;
        Woh[j] = __float2half(Wo[j]);
    }
    if (i < MVOA)
        ball[i] = (i < 512) ? bv[i] : (i < 768) ? boff[i - 512] : battn[i - 768];
}

// ---------------------------------------------------------------------------
// fp16 GEMM via mma.sync.m16n8k16, 128x128 tile, BK=32, 4-stage cp.async.
// (exact R10/R14 configuration — empirically fastest)
// ---------------------------------------------------------------------------
#define LDSM4(r, addr) \
    asm volatile("ldmatrix.sync.aligned.m8n8.x4.shared.b16 {%0,%1,%2,%3}, [%4];" \
                 : "=r"((r)[0]), "=r"((r)[1]), "=r"((r)[2]), "=r"((r)[3]) : "r"(addr))
#define LDSM4T(r, addr) \
    asm volatile("ldmatrix.sync.aligned.m8n8.x4.trans.shared.b16 {%0,%1,%2,%3}, [%4];" \
                 : "=r"((r)[0]), "=r"((r)[1]), "=r"((r)[2]), "=r"((r)[3]) : "r"(addr))
#define MMA16816H(c, a, b) \
    asm volatile("mma.sync.aligned.m16n8k16.row.col.f32.f16.f16.f32 " \
                 "{%0,%1,%2,%3}, {%4,%5,%6,%7}, {%8,%9}, {%0,%1,%2,%3};" \
                 : "+f"((c)[0]), "+f"((c)[1]), "+f"((c)[2]), "+f"((c)[3]) \
                 : "r"((a)[0]), "r"((a)[1]), "r"((a)[2]), "r"((a)[3]), \
                   "r"((b)[0]), "r"((b)[1]))

#define STAGE_BYTES 18944
#define SMEM_GEMM   (4 * STAGE_BYTES)

template<int MODE>
__global__ __launch_bounds__(256, 2)
void gemm_fp16_kernel(const __half* __restrict__ A,
                      const __half* __restrict__ W,
                      const float* __restrict__ bias, void* __restrict__ Cout,
                      void* __restrict__ Cout2,
                      int N, int K, int M)
{
    extern __shared__ char smem[];
    const uint32_t sdata = (uint32_t)__cvta_generic_to_shared(smem);

    const int tid  = threadIdx.x;
    const int lane = tid & 31;
    const int wid  = tid >> 5;
    const int wm = (wid & 1) * 64;
    const int wn = (wid >> 1) * 32;
    const int rowBase = blockIdx.y * 128;
    const int colBase = blockIdx.x * 128;

    const int lrowA = lane & 15;
    const int lcolA = (lane >> 4) * 8;
    const uint32_t aFragOff = (uint32_t)((wm + lrowA) * 80 + lcolA * 2);
    const int grp = lane >> 3;
    const int rB  = lane & 7;
    const uint32_t bFragOff = (uint32_t)(10240 + ((grp & 1) * 8 + rB) * 272 + (grp >> 1) * 16 + wn * 2);

    const int T = K >> 5;

    float acc[4][4][4];
#pragma unroll
    for (int i = 0; i < 4; i++)
#pragma unroll
        for (int j = 0; j < 4; j++)
#pragma unroll
            for (int r = 0; r < 4; r++) acc[i][j][r] = 0.f;

    auto loadStage = [&](int t, int stage) {
        int kp0 = t << 5;
        uint32_t sb = sdata + stage * STAGE_BYTES;
#pragma unroll
        for (int i = 0; i < 2; i++) {
            int id = tid * 2 + i;
            int r = id >> 2, c = id & 3;
            int gr = rowBase + r;
            const void* src = (const void*)(A + (size_t)gr * K + kp0 + c * 8);
            uint32_t dst = sb + r * 80 + c * 16;
            int sz = (gr < N) ? 16 : 0;
            asm volatile("cp.async.cg.shared.global [%0], [%1], 16, %2;"
                         :: "r"(dst), "l"(src), "r"(sz));
        }
#pragma unroll
        for (int i = 0; i < 2; i++) {
            int id = tid * 2 + i;
            int r = id >> 4, c = id & 15;
            const void* src = (const void*)(W + (size_t)(kp0 + r) * M + colBase + c * 8);
            uint32_t dst = sb + 10240 + r * 272 + c * 16;
            asm volatile("cp.async.cg.shared.global [%0], [%1], 16;"
                         :: "r"(dst), "l"(src));
        }
        asm volatile("cp.async.commit_group;" ::: "memory");
    };

    loadStage(0, 0);
    if (T > 1) loadStage(1, 1);
    if (T > 2) loadStage(2, 2);

    for (int t = 0; t < T; t++) {
        int rem = T - 1 - t;
        if (rem >= 2)      asm volatile("cp.async.wait_group 2;" ::: "memory");
        else if (rem == 1) asm volatile("cp.async.wait_group 1;" ::: "memory");
        else               asm volatile("cp.async.wait_group 0;" ::: "memory");
        __syncthreads();

        if (t + 3 < T) loadStage(t + 3, (t + 3) & 3);

        uint32_t sb = sdata + (t & 3) * STAGE_BYTES;
        uint32_t aBase = sb + aFragOff;
        uint32_t bBase = sb + bFragOff;
#pragma unroll
        for (int ks = 0; ks < 2; ks++) {
            uint32_t af[4][4];
            uint32_t bfr[4][2];
            uint32_t aB = aBase + ks * 32;
            uint32_t bB = bBase + ks * 4352;
#pragma unroll
            for (int mt = 0; mt < 4; mt++) LDSM4(af[mt], aB + mt * 1280);
#pragma unroll
            for (int np = 0; np < 2; np++) {
                uint32_t r4[4];
                LDSM4T(r4, bB + np * 32);
                bfr[np * 2][0] = r4[0]; bfr[np * 2][1] = r4[1];
                bfr[np * 2 + 1][0] = r4[2]; bfr[np * 2 + 1][1] = r4[3];
            }
#pragma unroll
            for (int mt = 0; mt < 4; mt++)
#pragma unroll
                for (int nt = 0; nt < 4; nt++)
                    MMA16816H(acc[mt][nt], af[mt], bfr[nt]);
        }
    }

    // epilogue
    const int mr = lane >> 2;
    const int nc = (lane & 3) * 2;
    const bool vpart = (MODE == 2) && (colBase < 512);

#pragma unroll
    for (int mt = 0; mt < 4; mt++) {
#pragma unroll
        for (int nt = 0; nt < 4; nt++) {
            int n0 = colBase + wn + nt * 8 + nc;
            float bb0 = bias[n0], bb1 = bias[n0 + 1];
#pragma unroll
            for (int half = 0; half < 2; half++) {
                int m = rowBase + wm + mt * 16 + mr + half * 8;
                if (m >= N) continue;
                float v0 = acc[mt][nt][half * 2 + 0] + bb0;
                float v1 = acc[mt][nt][half * 2 + 1] + bb1;
                if (MODE == 0) {
                    *reinterpret_cast<float2*>((float*)Cout + (size_t)m * M + n0) = make_float2(v0, v1);
                } else if (MODE == 1 || MODE == 3) {
                    if (MODE == 1) { v0 = fmaxf(v0, 0.f); v1 = fmaxf(v1, 0.f); }
                    __half2 hv; hv.x = __float2half(v0); hv.y = __float2half(v1);
                    *reinterpret_cast<__half2*>((__half*)Cout + (size_t)m * M + n0) = hv;
                } else {
                    if (vpart) {
                        __half2 hv; hv.x = __float2half(v0); hv.y = __float2half(v1);
                        *reinterpret_cast<__half2*>((__half*)Cout + (size_t)m * Dm + n0) = hv;
                    } else {
                        *reinterpret_cast<float2*>((float*)Cout2 + (size_t)m * MOA2 + (n0 - 512)) = make_float2(v0, v1);
                    }
                }
            }
        }
    }
}

// ---------------------------------------------------------------------------
// Two-phase deformable sampling. Block = 1 token (256 threads).
// Phase 1 (128 thr, one per head x sample): softmax via half-warp shuffles,
//   compute 4 corner (byte-offset, fused weight) pairs -> smem int2[512].
// Phase 2 (8 warps, warp per head, lane per channel-pair): 64 broadcast
//   LDS.64 + gather + FMA.
// ---------------------------------------------------------------------------
__global__ __launch_bounds__(256)
void sample_kernel(const __half* __restrict__ Vh, const float* __restrict__ OA,
                   const float* __restrict__ REF, __half* __restrict__ ACCh)
{
    __shared__ int2 sP[512];      // [(h*16+sk)*4 + c] = {byte_off, weight}

    const int n   = blockIdx.x;
    const int tid = threadIdx.x;
    const int b   = n / LQ;

    if (tid < 128) {
        int h  = tid >> 4;
        int sk = tid & 15;
        int s  = sk >> 2;

        float lg = OA[(size_t)n * MOA2 + 256 + h * 16 + sk];
        // softmax over the 16-thread group (half-warp butterflies)
        float mx = lg;
#pragma unroll
        for (int o = 8; o > 0; o >>= 1) mx = fmaxf(mx, __shfl_xor_sync(0xffffffffu, mx, o));
        float e = __expf(lg - mx);
        float ssum = e;
#pragma unroll
        for (int o = 8; o > 0; o >>= 1) ssum += __shfl_xor_sync(0xffffffffu, ssum, o);
        float w = e / ssum;

        float refx = REF[(size_t)n * 2 + 0];
        float refy = REF[(size_t)n * 2 + 1];
        float2 oxy = *reinterpret_cast<const float2*>(OA + (size_t)n * MOA2 + h * 32 + sk * 2);

        int wl = c_wl[s], hl = c_hl[s];
        int base_tok = b * LQ + c_offs[s];
        float x = refx * (float)wl + oxy.x - 0.5f;
        float y = refy * (float)hl + oxy.y - 0.5f;
        float x0f = floorf(x), y0f = floorf(y);
        int x0 = (int)x0f, y0 = (int)y0f;
        float wx1 = x - x0f, wx0 = 1.f - wx1;
        float wy1 = y - y0f, wy0 = 1.f - wy1;

#pragma unroll
        for (int c = 0; c < 4; c++) {
            int xi = x0 + (c & 1);
            int yi = y0 + (c >> 1);
            bool valid = (xi >= 0) && (xi < wl) && (yi >= 0) && (yi < hl);
            int xc = min(max(xi, 0), wl - 1);
            int yc = min(max(yi, 0), hl - 1);
            float wc = w * ((c & 1) ? wx1 : wx0) * ((c >> 1) ? wy1 : wy0);
            int off = (base_tok + yc * wl + xc) * (Dm * 2) + h * (DHh * 2);  // bytes
            int2 pk;
            pk.x = off;
            pk.y = __float_as_int(valid ? wc : 0.f);
            sP[tid * 4 + c] = pk;
        }
    }
    __syncthreads();

    const int h    = tid >> 5;
    const int lane = tid & 31;
    const char* vb = (const char*)Vh + lane * 4;   // lane's half2 within the head row

    float acc0 = 0.f, acc1 = 0.f;
#pragma unroll 8
    for (int i = 0; i < 64; i++) {
        int2 pk = sP[h * 64 + i];                   // broadcast LDS.64
        float w = __int_as_float(pk.y);
        __half2 hv = *reinterpret_cast<const __half2*>(vb + pk.x);
        float2 fv = __half22float2(hv);
        acc0 = fmaf(w, fv.x, acc0);
        acc1 = fmaf(w, fv.y, acc1);
    }
    size_t basep = (size_t)n * Dm + h * DHh;
    __half2 hv; hv.x = __float2half(acc0); hv.y = __float2half(acc1);
    *reinterpret_cast<__half2*>(ACCh + basep + 2 * lane) = hv;
}

// ---------------------------------------------------------------------------
// Fused residual-add + LayerNorm, fp16 inputs; fp16 and/or fp32 outputs.
// ---------------------------------------------------------------------------
__global__ void add_layernorm_h_kernel(const __half* __restrict__ A, const __half* __restrict__ Bv,
                                       const float* __restrict__ g, const float* __restrict__ be,
                                       __half* __restrict__ outh, float* __restrict__ outf)
{
    int n = blockIdx.x;
    int t = threadIdx.x;
    float v[4];
    float s = 0.f, ss = 0.f;
    const __half2* a2 = reinterpret_cast<const __half2*>(A + (size_t)n * Dm);
    const __half2* b2 = reinterpret_cast<const __half2*>(Bv + (size_t)n * Dm);
#pragma unroll
    for (int i = 0; i < 2; i++) {
        int d2 = t + i * 128;
        float2 fa = __half22float2(a2[d2]);
        float2 fb = __half22float2(b2[d2]);
        float x0 = fa.x + fb.x, x1 = fa.y + fb.y;
        v[i * 2] = x0; v[i * 2 + 1] = x1;
        s += x0 + x1; ss += x0 * x0 + x1 * x1;
    }
#pragma unroll
    for (int o = 16; o > 0; o >>= 1) {
        s  += __shfl_xor_sync(0xffffffffu, s,  o);
        ss += __shfl_xor_sync(0xffffffffu, ss, o);
    }
    __shared__ float sh[8];
    int w = t >> 5, ln = t & 31;
    if (ln == 0) { sh[w] = s; sh[4 + w] = ss; }
    __syncthreads();
    float ts  = sh[0] + sh[1] + sh[2] + sh[3];
    float tss = sh[4] + sh[5] + sh[6] + sh[7];
    float mu  = ts * (1.f / Dm);
    float var = tss * (1.f / Dm) - mu * mu;
    float inv = rsqrtf(var + 1e-5f);
#pragma unroll
    for (int i = 0; i < 2; i++) {
        int d2 = t + i * 128;
        int d = d2 * 2;
        float o0 = (v[i * 2]     - mu) * inv * g[d]     + be[d];
        float o1 = (v[i * 2 + 1] - mu) * inv * g[d + 1] + be[d + 1];
        if (outh) {
            __half2 hv; hv.x = __float2half(o0); hv.y = __float2half(o1);
            *reinterpret_cast<__half2*>(outh + (size_t)n * Dm + d) = hv;
        }
        if (outf) {
            *reinterpret_cast<float2*>(outf + (size_t)n * Dm + d) = make_float2(o0, o1);
        }
    }
}

// ---------------------------------------------------------------------------
// Launch
// ---------------------------------------------------------------------------
extern "C" void kernel_launch(void* const* d_in, const int* in_sizes, int n_in,
                              void* d_out, int out_size)
{
    const float* srcs[4] = {nullptr, nullptr, nullptr, nullptr};
    const float* refs[4] = {nullptr, nullptr, nullptr, nullptr};
    const int src_sz[4] = {Bb * 56 * 56 * Dm, Bb * 28 * 28 * Dm, Bb * 14 * 14 * Dm, Bb * 7 * 7 * Dm};
    const int ref_sz[4] = {Bb * 56 * 56 * 2,  Bb * 28 * 28 * 2,  Bb * 14 * 14 * 2,  Bb * 7 * 7 * 2};
    for (int i = 0; i < 8; i++) {
        int sz = in_sizes[i];
        for (int l = 0; l < 4; l++) {
            if (sz == src_sz[l] && !srcs[l]) { srcs[l] = (const float*)d_in[i]; goto next; }
        }
        for (int l = 0; l < 4; l++) {
            if (sz == ref_sz[l] && !refs[l]) { refs[l] = (const float*)d_in[i]; goto next; }
        }
    next:;
    }

    const float* Wv    = (const float*)d_in[8];
    const float* bv    = (const float*)d_in[9];
    const float* Woff  = (const float*)d_in[10];
    const float* boff  = (const float*)d_in[11];
    const float* Wattn = (const float*)d_in[12];
    const float* battn = (const float*)d_in[13];
    const float* Wo    = (const float*)d_in[14];
    const float* bo    = (const float*)d_in[15];
    const float* W1    = (const float*)d_in[16];
    const float* b1    = (const float*)d_in[17];
    const float* W2    = (const float*)d_in[18];
    const float* b2    = (const float*)d_in[19];
    const float* g1    = (const float*)d_in[20];
    const float* be1   = (const float*)d_in[21];
    const float* g2    = (const float*)d_in[22];
    const float* be2   = (const float*)d_in[23];
    float* out = (float*)d_out;

    float *REF, *OA, *ball;
    __half *Qh, *Vh, *ACCh, *A2h, *Xh, *Hbh, *Yh, *Wah, *Woh, *W1h, *W2h;
    cudaGetSymbolAddress((void**)&REF,  g_REF);
    cudaGetSymbolAddress((void**)&OA,   g_OA);
    cudaGetSymbolAddress((void**)&ball, g_ball);
    cudaGetSymbolAddress((void**)&Qh,   g_Qh);
    cudaGetSymbolAddress((void**)&Vh,   g_Vh);
    cudaGetSymbolAddress((void**)&ACCh, g_ACCh);
    cudaGetSymbolAddress((void**)&A2h,  g_A2h);
    cudaGetSymbolAddress((void**)&Xh,   g_Xh);
    cudaGetSymbolAddress((void**)&Hbh,  g_Hbh);
    cudaGetSymbolAddress((void**)&Yh,   g_Yh);
    cudaGetSymbolAddress((void**)&Wah,  g_Wah);
    cudaGetSymbolAddress((void**)&Woh,  g_Woh);
    cudaGetSymbolAddress((void**)&W1h,  g_W1h);
    cudaGetSymbolAddress((void**)&W2h,  g_W2h);

    cudaFuncSetAttribute(gemm_fp16_kernel<0>, cudaFuncAttributeMaxDynamicSharedMemorySize, SMEM_GEMM);
    cudaFuncSetAttribute(gemm_fp16_kernel<1>, cudaFuncAttributeMaxDynamicSharedMemorySize, SMEM_GEMM);
    cudaFuncSetAttribute(gemm_fp16_kernel<2>, cudaFuncAttributeMaxDynamicSharedMemorySize, SMEM_GEMM);
    cudaFuncSetAttribute(gemm_fp16_kernel<3>, cudaFuncAttributeMaxDynamicSharedMemorySize, SMEM_GEMM);

    const int rowBlocks = (NTOK + 127) / 128;   // 131
    dim3 blk(256);

    // 0: ALL weight prep in one kernel
    {
        int total = N_WA + N_W1 + N_W2 + N_WO;
        prep_w_kernel<<<(total + 255) / 256, 256>>>(Wv, Woff, Wattn, bv, boff, battn,
                                                    W1, W2, Wo, Wah, ball, W1h, W2h, Woh);
    }
    // 1: pack (Q + REF folded)
    {
        int total = NTOK * (Dm / 4);
        pack_kernel<<<(total + 255) / 256, 256>>>(srcs[0], srcs[1], srcs[2], srcs[3],
                                                  refs[0], refs[1], refs[2], refs[3], Qh, REF);
    }
    // 2: [Vh | OA] = Q @ [Wv|Woff|Wattn] + bias
    gemm_fp16_kernel<2><<<dim3(MVOA / 128, rowBlocks), blk, SMEM_GEMM>>>(Qh, Wah, ball, Vh, OA, NTOK, Dm, MVOA);
    // 3: two-phase sampling (fused softmax) -> ACCh
    sample_kernel<<<NTOK, 256>>>(Vh, OA, REF, ACCh);
    // 4: A2h = ACC @ Wo + bo  (fp16 out)
    gemm_fp16_kernel<3><<<dim3(Dm / 128, rowBlocks), blk, SMEM_GEMM>>>(ACCh, Woh, bo, A2h, nullptr, NTOK, Dm, Dm);
    // 5: Xh = LN(Qh + A2h)
    add_layernorm_h_kernel<<<NTOK, 128>>>(Qh, A2h, g1, be1, Xh, nullptr);
    // 6: Hbh = fp16(relu(X @ W1 + b1))
    gemm_fp16_kernel<1><<<dim3(DFFm / 128, rowBlocks), blk, SMEM_GEMM>>>(Xh, W1h, b1, Hbh, nullptr, NTOK, Dm, DFFm);
    // 7: Yh = Hb @ W2 + b2  (fp16 out)
    gemm_fp16_kernel<3><<<dim3(Dm / 128, rowBlocks), blk, SMEM_GEMM>>>(Hbh, W2h, b2, Yh, nullptr, NTOK, DFFm, Dm);
    // 8: out = LN(Xh + Yh)  (fp32 to d_out)
    add_layernorm_h_kernel<<<NTOK, 128>>>(Xh, Yh, g2, be2, nullptr, out);
}

// round 16
// speedup vs baseline: 1.4445x; 1.0431x over previous
#include <cuda_runtime.h>
#include <cuda_fp16.h>
#include <cstdint>

// ---------------------------------------------------------------------------
// Problem constants
// ---------------------------------------------------------------------------
#define Dm    512
#define Hh    8
#define DHh   64
#define DFFm  2048
#define Kk    4
#define Ss    4
#define Bb    4
#define LQ    4165
#define NTOK  (Bb * LQ)     // 16660 (even)
#define MVOA  896
#define MOA2  384

__device__ __constant__ int c_wl[4]   = {56, 28, 14, 7};
__device__ __constant__ int c_hl[4]   = {56, 28, 14, 7};
__device__ __constant__ int c_offs[4] = {0, 3136, 3920, 4116};

// ---------------------------------------------------------------------------
// Scratch
// ---------------------------------------------------------------------------
__device__ float g_REF [(size_t)NTOK * 2];
__device__ float g_OA  [(size_t)NTOK * MOA2];
__device__ float g_ball[MVOA];

__device__ __half g_Qh  [(size_t)NTOK * Dm];
__device__ __half g_Vh  [(size_t)NTOK * Dm];
__device__ __half g_ACCh[(size_t)NTOK * Dm];
__device__ __half g_A2h [(size_t)NTOK * Dm];
__device__ __half g_Xh  [(size_t)NTOK * Dm];
__device__ __half g_Hbh [(size_t)NTOK * DFFm];
__device__ __half g_Yh  [(size_t)NTOK * Dm];
__device__ __half g_Wah [(size_t)Dm * MVOA];
__device__ __half g_Woh [(size_t)Dm * Dm];
__device__ __half g_W1h [(size_t)Dm * DFFm];
__device__ __half g_W2h [(size_t)DFFm * Dm];

// ---------------------------------------------------------------------------
__device__ __forceinline__ int scale_of(int p, int& loc) {
    if (p < 3136)      { loc = p;        return 0; }
    else if (p < 3920) { loc = p - 3136; return 1; }
    else if (p < 4116) { loc = p - 3920; return 2; }
    else               { loc = p - 4116; return 3; }
}

// ---------------------------------------------------------------------------
// pack: srcs -> Qh fp16; refs -> REF (folded)
// ---------------------------------------------------------------------------
__global__ void pack_kernel(const float* __restrict__ s0, const float* __restrict__ s1,
                            const float* __restrict__ s2, const float* __restrict__ s3,
                            const float* __restrict__ r0, const float* __restrict__ r1,
                            const float* __restrict__ r2, const float* __restrict__ r3,
                            __half* __restrict__ Qh, float* __restrict__ REF)
{
    int e = blockIdx.x * blockDim.x + threadIdx.x;
    const int total = NTOK * (Dm / 4);
    if (e >= total) return;
    int n  = e >> 7;
    int d4 = e & 127;
    int b = n / LQ;
    int p = n % LQ;
    int loc;
    int l = scale_of(p, loc);
    const float* src = (l == 0) ? s0 : (l == 1) ? s1 : (l == 2) ? s2 : s3;
    int lq = c_wl[l] * c_hl[l];
    float4 v = reinterpret_cast<const float4*>(src)[(size_t)(b * lq + loc) * 128 + d4];
    __half h[4] = {__float2half(v.x), __float2half(v.y), __float2half(v.z), __float2half(v.w)};
    *reinterpret_cast<uint2*>(Qh + (size_t)n * Dm + d4 * 4) = *reinterpret_cast<uint2*>(h);

    if (e < NTOK) {
        int nb = e / LQ, pp = e % LQ, lc;
        int ll = scale_of(pp, lc);
        const float* rsrc = (ll == 0) ? r0 : (ll == 1) ? r1 : (ll == 2) ? r2 : r3;
        int lq2 = c_wl[ll] * c_hl[ll];
        float2 rv = *reinterpret_cast<const float2*>(rsrc + (size_t)(nb * lq2 + lc) * 2);
        *reinterpret_cast<float2*>(REF + (size_t)e * 2) = rv;
    }
}

// ---------------------------------------------------------------------------
// ONE prep kernel: merged VOA weight+bias and W1/W2/Wo fp16 converts.
// ---------------------------------------------------------------------------
#define N_WA (Dm * MVOA)
#define N_W1 (Dm * DFFm)
#define N_W2 (DFFm * Dm)
#define N_WO (Dm * Dm)
__global__ void prep_w_kernel(const float* __restrict__ Wv, const float* __restrict__ Woff,
                              const float* __restrict__ Wattn,
                              const float* __restrict__ bv, const float* __restrict__ boff,
                              const float* __restrict__ battn,
                              const float* __restrict__ W1, const float* __restrict__ W2,
                              const float* __restrict__ Wo,
                              __half* __restrict__ Wah, float* __restrict__ ball,
                              __half* __restrict__ W1h, __half* __restrict__ W2h,
                              __half* __restrict__ Woh)
{
    int i = blockIdx.x * blockDim.x + threadIdx.x;
    if (i < N_WA) {
        int r = i / MVOA, c = i % MVOA;
        float w;
        if (c < 512)       w = Wv[r * 512 + c];
        else if (c < 768)  w = Woff[r * 256 + (c - 512)];
        else               w = Wattn[r * 128 + (c - 768)];
        Wah[i] = __float2half(w);
    } else if (i < N_WA + N_W1) {
        int j = i - N_WA;
        W1h[j] = __float2half(W1[j]);
    } else if (i < N_WA + N_W1 + N_W2) {
        int j = i - N_WA - N_W1;
        W2h[j] = __float2half(W2[j]);
    } else if (i < N_WA + N_W1 + N_W2 + N_WO) {
        int j = i - N_WA - N_W1 - N_W2;
        Woh[j] = __float2half(Wo[j]);
    }
    if (i < MVOA)
        ball[i] = (i < 512) ? bv[i] : (i < 768) ? boff[i - 512] : battn[i - 768];
}

// ---------------------------------------------------------------------------
// fp16 GEMM via mma.sync.m16n8k16, 128x128 tile, BK=32, 4-stage cp.async.
// (frozen R10/R14 configuration — empirically fastest)
// ---------------------------------------------------------------------------
#define LDSM4(r, addr) \
    asm volatile("ldmatrix.sync.aligned.m8n8.x4.shared.b16 {%0,%1,%2,%3}, [%4];" \
                 : "=r"((r)[0]), "=r"((r)[1]), "=r"((r)[2]), "=r"((r)[3]) : "r"(addr))
#define LDSM4T(r, addr) \
    asm volatile("ldmatrix.sync.aligned.m8n8.x4.trans.shared.b16 {%0,%1,%2,%3}, [%4];" \
                 : "=r"((r)[0]), "=r"((r)[1]), "=r"((r)[2]), "=r"((r)[3]) : "r"(addr))
#define MMA16816H(c, a, b) \
    asm volatile("mma.sync.aligned.m16n8k16.row.col.f32.f16.f16.f32 " \
                 "{%0,%1,%2,%3}, {%4,%5,%6,%7}, {%8,%9}, {%0,%1,%2,%3};" \
                 : "+f"((c)[0]), "+f"((c)[1]), "+f"((c)[2]), "+f"((c)[3]) \
                 : "r"((a)[0]), "r"((a)[1]), "r"((a)[2]), "r"((a)[3]), \
                   "r"((b)[0]), "r"((b)[1]))

#define STAGE_BYTES 18944
#define SMEM_GEMM   (4 * STAGE_BYTES)

template<int MODE>
__global__ __launch_bounds__(256, 2)
void gemm_fp16_kernel(const __half* __restrict__ A,
                      const __half* __restrict__ W,
                      const float* __restrict__ bias, void* __restrict__ Cout,
                      void* __restrict__ Cout2,
                      int N, int K, int M)
{
    extern __shared__ char smem[];
    const uint32_t sdata = (uint32_t)__cvta_generic_to_shared(smem);

    const int tid  = threadIdx.x;
    const int lane = tid & 31;
    const int wid  = tid >> 5;
    const int wm = (wid & 1) * 64;
    const int wn = (wid >> 1) * 32;
    const int rowBase = blockIdx.y * 128;
    const int colBase = blockIdx.x * 128;

    const int lrowA = lane & 15;
    const int lcolA = (lane >> 4) * 8;
    const uint32_t aFragOff = (uint32_t)((wm + lrowA) * 80 + lcolA * 2);
    const int grp = lane >> 3;
    const int rB  = lane & 7;
    const uint32_t bFragOff = (uint32_t)(10240 + ((grp & 1) * 8 + rB) * 272 + (grp >> 1) * 16 + wn * 2);

    const int T = K >> 5;

    float acc[4][4][4];
#pragma unroll
    for (int i = 0; i < 4; i++)
#pragma unroll
        for (int j = 0; j < 4; j++)
#pragma unroll
            for (int r = 0; r < 4; r++) acc[i][j][r] = 0.f;

    auto loadStage = [&](int t, int stage) {
        int kp0 = t << 5;
        uint32_t sb = sdata + stage * STAGE_BYTES;
#pragma unroll
        for (int i = 0; i < 2; i++) {
            int id = tid * 2 + i;
            int r = id >> 2, c = id & 3;
            int gr = rowBase + r;
            const void* src = (const void*)(A + (size_t)gr * K + kp0 + c * 8);
            uint32_t dst = sb + r * 80 + c * 16;
            int sz = (gr < N) ? 16 : 0;
            asm volatile("cp.async.cg.shared.global [%0], [%1], 16, %2;"
                         :: "r"(dst), "l"(src), "r"(sz));
        }
#pragma unroll
        for (int i = 0; i < 2; i++) {
            int id = tid * 2 + i;
            int r = id >> 4, c = id & 15;
            const void* src = (const void*)(W + (size_t)(kp0 + r) * M + colBase + c * 8);
            uint32_t dst = sb + 10240 + r * 272 + c * 16;
            asm volatile("cp.async.cg.shared.global [%0], [%1], 16;"
                         :: "r"(dst), "l"(src));
        }
        asm volatile("cp.async.commit_group;" ::: "memory");
    };

    loadStage(0, 0);
    if (T > 1) loadStage(1, 1);
    if (T > 2) loadStage(2, 2);

    for (int t = 0; t < T; t++) {
        int rem = T - 1 - t;
        if (rem >= 2)      asm volatile("cp.async.wait_group 2;" ::: "memory");
        else if (rem == 1) asm volatile("cp.async.wait_group 1;" ::: "memory");
        else               asm volatile("cp.async.wait_group 0;" ::: "memory");
        __syncthreads();

        if (t + 3 < T) loadStage(t + 3, (t + 3) & 3);

        uint32_t sb = sdata + (t & 3) * STAGE_BYTES;
        uint32_t aBase = sb + aFragOff;
        uint32_t bBase = sb + bFragOff;
#pragma unroll
        for (int ks = 0; ks < 2; ks++) {
            uint32_t af[4][4];
            uint32_t bfr[4][2];
            uint32_t aB = aBase + ks * 32;
            uint32_t bB = bBase + ks * 4352;
#pragma unroll
            for (int mt = 0; mt < 4; mt++) LDSM4(af[mt], aB + mt * 1280);
#pragma unroll
            for (int np = 0; np < 2; np++) {
                uint32_t r4[4];
                LDSM4T(r4, bB + np * 32);
                bfr[np * 2][0] = r4[0]; bfr[np * 2][1] = r4[1];
                bfr[np * 2 + 1][0] = r4[2]; bfr[np * 2 + 1][1] = r4[3];
            }
#pragma unroll
            for (int mt = 0; mt < 4; mt++)
#pragma unroll
                for (int nt = 0; nt < 4; nt++)
                    MMA16816H(acc[mt][nt], af[mt], bfr[nt]);
        }
    }

    // epilogue
    const int mr = lane >> 2;
    const int nc = (lane & 3) * 2;
    const bool vpart = (MODE == 2) && (colBase < 512);

#pragma unroll
    for (int mt = 0; mt < 4; mt++) {
#pragma unroll
        for (int nt = 0; nt < 4; nt++) {
            int n0 = colBase + wn + nt * 8 + nc;
            float bb0 = bias[n0], bb1 = bias[n0 + 1];
#pragma unroll
            for (int half = 0; half < 2; half++) {
                int m = rowBase + wm + mt * 16 + mr + half * 8;
                if (m >= N) continue;
                float v0 = acc[mt][nt][half * 2 + 0] + bb0;
                float v1 = acc[mt][nt][half * 2 + 1] + bb1;
                if (MODE == 0) {
                    *reinterpret_cast<float2*>((float*)Cout + (size_t)m * M + n0) = make_float2(v0, v1);
                } else if (MODE == 1 || MODE == 3) {
                    if (MODE == 1) { v0 = fmaxf(v0, 0.f); v1 = fmaxf(v1, 0.f); }
                    __half2 hv; hv.x = __float2half(v0); hv.y = __float2half(v1);
                    *reinterpret_cast<__half2*>((__half*)Cout + (size_t)m * M + n0) = hv;
                } else {
                    if (vpart) {
                        __half2 hv; hv.x = __float2half(v0); hv.y = __float2half(v1);
                        *reinterpret_cast<__half2*>((__half*)Cout + (size_t)m * Dm + n0) = hv;
                    } else {
                        *reinterpret_cast<float2*>((float*)Cout2 + (size_t)m * MOA2 + (n0 - 512)) = make_float2(v0, v1);
                    }
                }
            }
        }
    }
}

// ---------------------------------------------------------------------------
// Two-phase deformable sampling, 2 tokens per block, 2 heads per warp.
// Phase 1 (256 thr = 2 tokens x 128): softmax + corner (offset, weight) -> smem.
// Phase 2: warp w -> token (w>>2), heads (w&3)*2 + (lane>>4); lane&15 covers
//   4 channels via one LDG.64 per corner.
// ---------------------------------------------------------------------------
__global__ __launch_bounds__(256)
void sample_kernel(const __half* __restrict__ Vh, const float* __restrict__ OA,
                   const float* __restrict__ REF, __half* __restrict__ ACCh)
{
    __shared__ int2 sP[2][512];   // [token][(h*16+sk)*4 + c] = {byte_off, weight}

    const int n0  = blockIdx.x * 2;
    const int tid = threadIdx.x;

    // ---- Phase 1: all 256 threads, one per (token, head, sample)
    {
        int t  = tid >> 7;            // 0,1
        int r  = tid & 127;
        int n  = n0 + t;
        int b  = n / LQ;
        int h  = r >> 4;
        int sk = r & 15;
        int s  = sk >> 2;

        float lg = OA[(size_t)n * MOA2 + 256 + h * 16 + sk];
        float mx = lg;
#pragma unroll
        for (int o = 8; o > 0; o >>= 1) mx = fmaxf(mx, __shfl_xor_sync(0xffffffffu, mx, o));
        float e = __expf(lg - mx);
        float ssum = e;
#pragma unroll
        for (int o = 8; o > 0; o >>= 1) ssum += __shfl_xor_sync(0xffffffffu, ssum, o);
        float w = e / ssum;

        float refx = REF[(size_t)n * 2 + 0];
        float refy = REF[(size_t)n * 2 + 1];
        float2 oxy = *reinterpret_cast<const float2*>(OA + (size_t)n * MOA2 + h * 32 + sk * 2);

        int wl = c_wl[s], hl = c_hl[s];
        int base_tok = b * LQ + c_offs[s];
        float x = refx * (float)wl + oxy.x - 0.5f;
        float y = refy * (float)hl + oxy.y - 0.5f;
        float x0f = floorf(x), y0f = floorf(y);
        int x0 = (int)x0f, y0 = (int)y0f;
        float wx1 = x - x0f, wx0 = 1.f - wx1;
        float wy1 = y - y0f, wy0 = 1.f - wy1;

#pragma unroll
        for (int c = 0; c < 4; c++) {
            int xi = x0 + (c & 1);
            int yi = y0 + (c >> 1);
            bool valid = (xi >= 0) && (xi < wl) && (yi >= 0) && (yi < hl);
            int xc = min(max(xi, 0), wl - 1);
            int yc = min(max(yi, 0), hl - 1);
            float wc = w * ((c & 1) ? wx1 : wx0) * ((c >> 1) ? wy1 : wy0);
            int off = (base_tok + yc * wl + xc) * (Dm * 2) + h * (DHh * 2);
            int2 pk;
            pk.x = off;
            pk.y = __float_as_int(valid ? wc : 0.f);
            sP[t][r * 4 + c] = pk;
        }
    }
    __syncthreads();

    // ---- Phase 2: warp per (token, head-pair); half-warp per head; 4 ch/lane
    const int w    = tid >> 5;
    const int lane = tid & 31;
    const int t    = w >> 2;
    const int n    = n0 + t;
    const int h    = (w & 3) * 2 + (lane >> 4);
    const int l4   = lane & 15;
    const char* vb = (const char*)Vh + l4 * 8;   // lane's 4 channels (8 bytes)

    float a0 = 0.f, a1 = 0.f, a2 = 0.f, a3 = 0.f;
#pragma unroll 8
    for (int i = 0; i < 64; i++) {
        int2 pk = sP[t][h * 64 + i];
        float wg = __int_as_float(pk.y);
        uint2 d = *reinterpret_cast<const uint2*>(vb + pk.x);
        __half2 h0 = *reinterpret_cast<__half2*>(&d.x);
        __half2 h1 = *reinterpret_cast<__half2*>(&d.y);
        float2 f0 = __half22float2(h0);
        float2 f1 = __half22float2(h1);
        a0 = fmaf(wg, f0.x, a0);
        a1 = fmaf(wg, f0.y, a1);
        a2 = fmaf(wg, f1.x, a2);
        a3 = fmaf(wg, f1.y, a3);
    }
    __half2 o0; o0.x = __float2half(a0); o0.y = __float2half(a1);
    __half2 o1; o1.x = __float2half(a2); o1.y = __float2half(a3);
    uint2 ov;
    ov.x = *reinterpret_cast<uint32_t*>(&o0);
    ov.y = *reinterpret_cast<uint32_t*>(&o1);
    *reinterpret_cast<uint2*>(ACCh + (size_t)n * Dm + h * DHh + l4 * 4) = ov;
}

// ---------------------------------------------------------------------------
// Fused residual-add + LayerNorm, fp16 inputs; fp16 and/or fp32 outputs.
// ---------------------------------------------------------------------------
__global__ void add_layernorm_h_kernel(const __half* __restrict__ A, const __half* __restrict__ Bv,
                                       const float* __restrict__ g, const float* __restrict__ be,
                                       __half* __restrict__ outh, float* __restrict__ outf)
{
    int n = blockIdx.x;
    int t = threadIdx.x;
    float v[4];
    float s = 0.f, ss = 0.f;
    const __half2* a2 = reinterpret_cast<const __half2*>(A + (size_t)n * Dm);
    const __half2* b2 = reinterpret_cast<const __half2*>(Bv + (size_t)n * Dm);
#pragma unroll
    for (int i = 0; i < 2; i++) {
        int d2 = t + i * 128;
        float2 fa = __half22float2(a2[d2]);
        float2 fb = __half22float2(b2[d2]);
        float x0 = fa.x + fb.x, x1 = fa.y + fb.y;
        v[i * 2] = x0; v[i * 2 + 1] = x1;
        s += x0 + x1; ss += x0 * x0 + x1 * x1;
    }
#pragma unroll
    for (int o = 16; o > 0; o >>= 1) {
        s  += __shfl_xor_sync(0xffffffffu, s,  o);
        ss += __shfl_xor_sync(0xffffffffu, ss, o);
    }
    __shared__ float sh[8];
    int w = t >> 5, ln = t & 31;
    if (ln == 0) { sh[w] = s; sh[4 + w] = ss; }
    __syncthreads();
    float ts  = sh[0] + sh[1] + sh[2] + sh[3];
    float tss = sh[4] + sh[5] + sh[6] + sh[7];
    float mu  = ts * (1.f / Dm);
    float var = tss * (1.f / Dm) - mu * mu;
    float inv = rsqrtf(var + 1e-5f);
#pragma unroll
    for (int i = 0; i < 2; i++) {
        int d2 = t + i * 128;
        int d = d2 * 2;
        float o0 = (v[i * 2]     - mu) * inv * g[d]     + be[d];
        float o1 = (v[i * 2 + 1] - mu) * inv * g[d + 1] + be[d + 1];
        if (outh) {
            __half2 hv; hv.x = __float2half(o0); hv.y = __float2half(o1);
            *reinterpret_cast<__half2*>(outh + (size_t)n * Dm + d) = hv;
        }
        if (outf) {
            *reinterpret_cast<float2*>(outf + (size_t)n * Dm + d) = make_float2(o0, o1);
        }
    }
}

// ---------------------------------------------------------------------------
// Launch
// ---------------------------------------------------------------------------
extern "C" void kernel_launch(void* const* d_in, const int* in_sizes, int n_in,
                              void* d_out, int out_size)
{
    const float* srcs[4] = {nullptr, nullptr, nullptr, nullptr};
    const float* refs[4] = {nullptr, nullptr, nullptr, nullptr};
    const int src_sz[4] = {Bb * 56 * 56 * Dm, Bb * 28 * 28 * Dm, Bb * 14 * 14 * Dm, Bb * 7 * 7 * Dm};
    const int ref_sz[4] = {Bb * 56 * 56 * 2,  Bb * 28 * 28 * 2,  Bb * 14 * 14 * 2,  Bb * 7 * 7 * 2};
    for (int i = 0; i < 8; i++) {
        int sz = in_sizes[i];
        for (int l = 0; l < 4; l++) {
            if (sz == src_sz[l] && !srcs[l]) { srcs[l] = (const float*)d_in[i]; goto next; }
        }
        for (int l = 0; l < 4; l++) {
            if (sz == ref_sz[l] && !refs[l]) { refs[l] = (const float*)d_in[i]; goto next; }
        }
    next:;
    }

    const float* Wv    = (const float*)d_in[8];
    const float* bv    = (const float*)d_in[9];
    const float* Woff  = (const float*)d_in[10];
    const float* boff  = (const float*)d_in[11];
    const float* Wattn = (const float*)d_in[12];
    const float* battn = (const float*)d_in[13];
    const float* Wo    = (const float*)d_in[14];
    const float* bo    = (const float*)d_in[15];
    const float* W1    = (const float*)d_in[16];
    const float* b1    = (const float*)d_in[17];
    const float* W2    = (const float*)d_in[18];
    const float* b2    = (const float*)d_in[19];
    const float* g1    = (const float*)d_in[20];
    const float* be1   = (const float*)d_in[21];
    const float* g2    = (const float*)d_in[22];
    const float* be2   = (const float*)d_in[23];
    float* out = (float*)d_out;

    float *REF, *OA, *ball;
    __half *Qh, *Vh, *ACCh, *A2h, *Xh, *Hbh, *Yh, *Wah, *Woh, *W1h, *W2h;
    cudaGetSymbolAddress((void**)&REF,  g_REF);
    cudaGetSymbolAddress((void**)&OA,   g_OA);
    cudaGetSymbolAddress((void**)&ball, g_ball);
    cudaGetSymbolAddress((void**)&Qh,   g_Qh);
    cudaGetSymbolAddress((void**)&Vh,   g_Vh);
    cudaGetSymbolAddress((void**)&ACCh, g_ACCh);
    cudaGetSymbolAddress((void**)&A2h,  g_A2h);
    cudaGetSymbolAddress((void**)&Xh,   g_Xh);
    cudaGetSymbolAddress((void**)&Hbh,  g_Hbh);
    cudaGetSymbolAddress((void**)&Yh,   g_Yh);
    cudaGetSymbolAddress((void**)&Wah,  g_Wah);
    cudaGetSymbolAddress((void**)&Woh,  g_Woh);
    cudaGetSymbolAddress((void**)&W1h,  g_W1h);
    cudaGetSymbolAddress((void**)&W2h,  g_W2h);

    cudaFuncSetAttribute(gemm_fp16_kernel<0>, cudaFuncAttributeMaxDynamicSharedMemorySize, SMEM_GEMM);
    cudaFuncSetAttribute(gemm_fp16_kernel<1>, cudaFuncAttributeMaxDynamicSharedMemorySize, SMEM_GEMM);
    cudaFuncSetAttribute(gemm_fp16_kernel<2>, cudaFuncAttributeMaxDynamicSharedMemorySize, SMEM_GEMM);
    cudaFuncSetAttribute(gemm_fp16_kernel<3>, cudaFuncAttributeMaxDynamicSharedMemorySize, SMEM_GEMM);

    const int rowBlocks = (NTOK + 127) / 128;   // 131
    dim3 blk(256);

    // 0: ALL weight prep in one kernel
    {
        int total = N_WA + N_W1 + N_W2 + N_WO;
        prep_w_kernel<<<(total + 255) / 256, 256>>>(Wv, Woff, Wattn, bv, boff, battn,
                                                    W1, W2, Wo, Wah, ball, W1h, W2h, Woh);
    }
    // 1: pack (Q + REF folded)
    {
        int total = NTOK * (Dm / 4);
        pack_kernel<<<(total + 255) / 256, 256>>>(srcs[0], srcs[1], srcs[2], srcs[3],
                                                  refs[0], refs[1], refs[2], refs[3], Qh, REF);
    }
    // 2: [Vh | OA] = Q @ [Wv|Woff|Wattn] + bias
    gemm_fp16_kernel<2><<<dim3(MVOA / 128, rowBlocks), blk, SMEM_GEMM>>>(Qh, Wah, ball, Vh, OA, NTOK, Dm, MVOA);
    // 3: two-phase sampling (2 tokens/block) -> ACCh
    sample_kernel<<<NTOK / 2, 256>>>(Vh, OA, REF, ACCh);
    // 4: A2h = ACC @ Wo + bo  (fp16 out)
    gemm_fp16_kernel<3><<<dim3(Dm / 128, rowBlocks), blk, SMEM_GEMM>>>(ACCh, Woh, bo, A2h, nullptr, NTOK, Dm, Dm);
    // 5: Xh = LN(Qh + A2h)
    add_layernorm_h_kernel<<<NTOK, 128>>>(Qh, A2h, g1, be1, Xh, nullptr);
    // 6: Hbh = fp16(relu(X @ W1 + b1))
    gemm_fp16_kernel<1><<<dim3(DFFm / 128, rowBlocks), blk, SMEM_GEMM>>>(Xh, W1h, b1, Hbh, nullptr, NTOK, Dm, DFFm);
    // 7: Yh = Hb @ W2 + b2  (fp16 out)
    gemm_fp16_kernel<3><<<dim3(Dm / 128, rowBlocks), blk, SMEM_GEMM>>>(Hbh, W2h, b2, Yh, nullptr, NTOK, DFFm, Dm);
    // 8: out = LN(Xh + Yh)  (fp32 to d_out)
    add_layernorm_h_kernel<<<NTOK, 128>>>(Xh, Yh, g2, be2, nullptr, out);
}

// round 17
// speedup vs baseline: 1.4657x; 1.0147x over previous
#include <cuda_runtime.h>
#include <cuda_fp16.h>
#include <cstdint>

// ---------------------------------------------------------------------------
// Problem constants
// ---------------------------------------------------------------------------
#define Dm    512
#define Hh    8
#define DHh   64
#define DFFm  2048
#define Kk    4
#define Ss    4
#define Bb    4
#define LQ    4165
#define NTOK  (Bb * LQ)     // 16660 (divisible by 4)
#define MVOA  896
#define MOA2  384

__device__ __constant__ int c_wl[4]   = {56, 28, 14, 7};
__device__ __constant__ int c_hl[4]   = {56, 28, 14, 7};
__device__ __constant__ int c_offs[4] = {0, 3136, 3920, 4116};

// ---------------------------------------------------------------------------
// Scratch
// ---------------------------------------------------------------------------
__device__ float g_REF [(size_t)NTOK * 2];
__device__ float g_OA  [(size_t)NTOK * MOA2];
__device__ float g_ball[MVOA];

__device__ __half g_Qh  [(size_t)NTOK * Dm];
__device__ __half g_Vh  [(size_t)NTOK * Dm];
__device__ __half g_ACCh[(size_t)NTOK * Dm];
__device__ __half g_A2h [(size_t)NTOK * Dm];
__device__ __half g_Xh  [(size_t)NTOK * Dm];
__device__ __half g_Hbh [(size_t)NTOK * DFFm];
__device__ __half g_Yh  [(size_t)NTOK * Dm];
__device__ __half g_Wah [(size_t)Dm * MVOA];
__device__ __half g_Woh [(size_t)Dm * Dm];
__device__ __half g_W1h [(size_t)Dm * DFFm];
__device__ __half g_W2h [(size_t)DFFm * Dm];

// ---------------------------------------------------------------------------
__device__ __forceinline__ int scale_of(int p, int& loc) {
    if (p < 3136)      { loc = p;        return 0; }
    else if (p < 3920) { loc = p - 3136; return 1; }
    else if (p < 4116) { loc = p - 3920; return 2; }
    else               { loc = p - 4116; return 3; }
}

// ---------------------------------------------------------------------------
// pack: srcs -> Qh fp16; refs -> REF (folded)
// ---------------------------------------------------------------------------
__global__ void pack_kernel(const float* __restrict__ s0, const float* __restrict__ s1,
                            const float* __restrict__ s2, const float* __restrict__ s3,
                            const float* __restrict__ r0, const float* __restrict__ r1,
                            const float* __restrict__ r2, const float* __restrict__ r3,
                            __half* __restrict__ Qh, float* __restrict__ REF)
{
    int e = blockIdx.x * blockDim.x + threadIdx.x;
    const int total = NTOK * (Dm / 4);
    if (e >= total) return;
    int n  = e >> 7;
    int d4 = e & 127;
    int b = n / LQ;
    int p = n % LQ;
    int loc;
    int l = scale_of(p, loc);
    const float* src = (l == 0) ? s0 : (l == 1) ? s1 : (l == 2) ? s2 : s3;
    int lq = c_wl[l] * c_hl[l];
    float4 v = reinterpret_cast<const float4*>(src)[(size_t)(b * lq + loc) * 128 + d4];
    __half h[4] = {__float2half(v.x), __float2half(v.y), __float2half(v.z), __float2half(v.w)};
    *reinterpret_cast<uint2*>(Qh + (size_t)n * Dm + d4 * 4) = *reinterpret_cast<uint2*>(h);

    if (e < NTOK) {
        int nb = e / LQ, pp = e % LQ, lc;
        int ll = scale_of(pp, lc);
        const float* rsrc = (ll == 0) ? r0 : (ll == 1) ? r1 : (ll == 2) ? r2 : r3;
        int lq2 = c_wl[ll] * c_hl[ll];
        float2 rv = *reinterpret_cast<const float2*>(rsrc + (size_t)(nb * lq2 + lc) * 2);
        *reinterpret_cast<float2*>(REF + (size_t)e * 2) = rv;
    }
}

// ---------------------------------------------------------------------------
// ONE prep kernel: merged VOA weight+bias and W1/W2/Wo fp16 converts.
// ---------------------------------------------------------------------------
#define N_WA (Dm * MVOA)
#define N_W1 (Dm * DFFm)
#define N_W2 (DFFm * Dm)
#define N_WO (Dm * Dm)
__global__ void prep_w_kernel(const float* __restrict__ Wv, const float* __restrict__ Woff,
                              const float* __restrict__ Wattn,
                              const float* __restrict__ bv, const float* __restrict__ boff,
                              const float* __restrict__ battn,
                              const float* __restrict__ W1, const float* __restrict__ W2,
                              const float* __restrict__ Wo,
                              __half* __restrict__ Wah, float* __restrict__ ball,
                              __half* __restrict__ W1h, __half* __restrict__ W2h,
                              __half* __restrict__ Woh)
{
    int i = blockIdx.x * blockDim.x + threadIdx.x;
    if (i < N_WA) {
        int r = i / MVOA, c = i % MVOA;
        float w;
        if (c < 512)       w = Wv[r * 512 + c];
        else if (c < 768)  w = Woff[r * 256 + (c - 512)];
        else               w = Wattn[r * 128 + (c - 768)];
        Wah[i] = __float2half(w);
    } else if (i < N_WA + N_W1) {
        int j = i - N_WA;
        W1h[j] = __float2half(W1[j]);
    } else if (i < N_WA + N_W1 + N_W2) {
        int j = i - N_WA - N_W1;
        W2h[j] = __float2half(W2[j]);
    } else if (i < N_WA + N_W1 + N_W2 + N_WO) {
        int j = i - N_WA - N_W1 - N_W2;
        Woh[j] = __float2half(Wo[j]);
    }
    if (i < MVOA)
        ball[i] = (i < 512) ? bv[i] : (i < 768) ? boff[i - 512] : battn[i - 768];
}

// ---------------------------------------------------------------------------
// fp16 GEMM via mma.sync.m16n8k16, 128x128 tile, BK=32, 4-stage cp.async.
// (frozen R10/R14 configuration — empirically fastest)
// ---------------------------------------------------------------------------
#define LDSM4(r, addr) \
    asm volatile("ldmatrix.sync.aligned.m8n8.x4.shared.b16 {%0,%1,%2,%3}, [%4];" \
                 : "=r"((r)[0]), "=r"((r)[1]), "=r"((r)[2]), "=r"((r)[3]) : "r"(addr))
#define LDSM4T(r, addr) \
    asm volatile("ldmatrix.sync.aligned.m8n8.x4.trans.shared.b16 {%0,%1,%2,%3}, [%4];" \
                 : "=r"((r)[0]), "=r"((r)[1]), "=r"((r)[2]), "=r"((r)[3]) : "r"(addr))
#define MMA16816H(c, a, b) \
    asm volatile("mma.sync.aligned.m16n8k16.row.col.f32.f16.f16.f32 " \
                 "{%0,%1,%2,%3}, {%4,%5,%6,%7}, {%8,%9}, {%0,%1,%2,%3};" \
                 : "+f"((c)[0]), "+f"((c)[1]), "+f"((c)[2]), "+f"((c)[3]) \
                 : "r"((a)[0]), "r"((a)[1]), "r"((a)[2]), "r"((a)[3]), \
                   "r"((b)[0]), "r"((b)[1]))

#define STAGE_BYTES 18944
#define SMEM_GEMM   (4 * STAGE_BYTES)

template<int MODE>
__global__ __launch_bounds__(256, 2)
void gemm_fp16_kernel(const __half* __restrict__ A,
                      const __half* __restrict__ W,
                      const float* __restrict__ bias, void* __restrict__ Cout,
                      void* __restrict__ Cout2,
                      int N, int K, int M)
{
    extern __shared__ char smem[];
    const uint32_t sdata = (uint32_t)__cvta_generic_to_shared(smem);

    const int tid  = threadIdx.x;
    const int lane = tid & 31;
    const int wid  = tid >> 5;
    const int wm = (wid & 1) * 64;
    const int wn = (wid >> 1) * 32;
    const int rowBase = blockIdx.y * 128;
    const int colBase = blockIdx.x * 128;

    const int lrowA = lane & 15;
    const int lcolA = (lane >> 4) * 8;
    const uint32_t aFragOff = (uint32_t)((wm + lrowA) * 80 + lcolA * 2);
    const int grp = lane >> 3;
    const int rB  = lane & 7;
    const uint32_t bFragOff = (uint32_t)(10240 + ((grp & 1) * 8 + rB) * 272 + (grp >> 1) * 16 + wn * 2);

    const int T = K >> 5;

    float acc[4][4][4];
#pragma unroll
    for (int i = 0; i < 4; i++)
#pragma unroll
        for (int j = 0; j < 4; j++)
#pragma unroll
            for (int r = 0; r < 4; r++) acc[i][j][r] = 0.f;

    auto loadStage = [&](int t, int stage) {
        int kp0 = t << 5;
        uint32_t sb = sdata + stage * STAGE_BYTES;
#pragma unroll
        for (int i = 0; i < 2; i++) {
            int id = tid * 2 + i;
            int r = id >> 2, c = id & 3;
            int gr = rowBase + r;
            const void* src = (const void*)(A + (size_t)gr * K + kp0 + c * 8);
            uint32_t dst = sb + r * 80 + c * 16;
            int sz = (gr < N) ? 16 : 0;
            asm volatile("cp.async.cg.shared.global [%0], [%1], 16, %2;"
                         :: "r"(dst), "l"(src), "r"(sz));
        }
#pragma unroll
        for (int i = 0; i < 2; i++) {
            int id = tid * 2 + i;
            int r = id >> 4, c = id & 15;
            const void* src = (const void*)(W + (size_t)(kp0 + r) * M + colBase + c * 8);
            uint32_t dst = sb + 10240 + r * 272 + c * 16;
            asm volatile("cp.async.cg.shared.global [%0], [%1], 16;"
                         :: "r"(dst), "l"(src));
        }
        asm volatile("cp.async.commit_group;" ::: "memory");
    };

    loadStage(0, 0);
    if (T > 1) loadStage(1, 1);
    if (T > 2) loadStage(2, 2);

    for (int t = 0; t < T; t++) {
        int rem = T - 1 - t;
        if (rem >= 2)      asm volatile("cp.async.wait_group 2;" ::: "memory");
        else if (rem == 1) asm volatile("cp.async.wait_group 1;" ::: "memory");
        else               asm volatile("cp.async.wait_group 0;" ::: "memory");
        __syncthreads();

        if (t + 3 < T) loadStage(t + 3, (t + 3) & 3);

        uint32_t sb = sdata + (t & 3) * STAGE_BYTES;
        uint32_t aBase = sb + aFragOff;
        uint32_t bBase = sb + bFragOff;
#pragma unroll
        for (int ks = 0; ks < 2; ks++) {
            uint32_t af[4][4];
            uint32_t bfr[4][2];
            uint32_t aB = aBase + ks * 32;
            uint32_t bB = bBase + ks * 4352;
#pragma unroll
            for (int mt = 0; mt < 4; mt++) LDSM4(af[mt], aB + mt * 1280);
#pragma unroll
            for (int np = 0; np < 2; np++) {
                uint32_t r4[4];
                LDSM4T(r4, bB + np * 32);
                bfr[np * 2][0] = r4[0]; bfr[np * 2][1] = r4[1];
                bfr[np * 2 + 1][0] = r4[2]; bfr[np * 2 + 1][1] = r4[3];
            }
#pragma unroll
            for (int mt = 0; mt < 4; mt++)
#pragma unroll
                for (int nt = 0; nt < 4; nt++)
                    MMA16816H(acc[mt][nt], af[mt], bfr[nt]);
        }
    }

    // epilogue
    const int mr = lane >> 2;
    const int nc = (lane & 3) * 2;
    const bool vpart = (MODE == 2) && (colBase < 512);

#pragma unroll
    for (int mt = 0; mt < 4; mt++) {
#pragma unroll
        for (int nt = 0; nt < 4; nt++) {
            int n0 = colBase + wn + nt * 8 + nc;
            float bb0 = bias[n0], bb1 = bias[n0 + 1];
#pragma unroll
            for (int half = 0; half < 2; half++) {
                int m = rowBase + wm + mt * 16 + mr + half * 8;
                if (m >= N) continue;
                float v0 = acc[mt][nt][half * 2 + 0] + bb0;
                float v1 = acc[mt][nt][half * 2 + 1] + bb1;
                if (MODE == 0) {
                    *reinterpret_cast<float2*>((float*)Cout + (size_t)m * M + n0) = make_float2(v0, v1);
                } else if (MODE == 1 || MODE == 3) {
                    if (MODE == 1) { v0 = fmaxf(v0, 0.f); v1 = fmaxf(v1, 0.f); }
                    __half2 hv; hv.x = __float2half(v0); hv.y = __float2half(v1);
                    *reinterpret_cast<__half2*>((__half*)Cout + (size_t)m * M + n0) = hv;
                } else {
                    if (vpart) {
                        __half2 hv; hv.x = __float2half(v0); hv.y = __float2half(v1);
                        *reinterpret_cast<__half2*>((__half*)Cout + (size_t)m * Dm + n0) = hv;
                    } else {
                        *reinterpret_cast<float2*>((float*)Cout2 + (size_t)m * MOA2 + (n0 - 512)) = make_float2(v0, v1);
                    }
                }
            }
        }
    }
}

// ---------------------------------------------------------------------------
// Two-phase deformable sampling, 4 tokens per block.
// Phase 1 (256 thr x 2 iters): softmax + corner (offset, weight) -> smem,
//   per-head stride padded to 66 int2 (kills cross-head bank conflicts).
// Phase 2: 8 warps; warp w -> token (w>>1); head = (w&1)*4 + (lane>>3);
//   lane&7 covers 8 channels via one LDG.128 per corner.
// ---------------------------------------------------------------------------
#define HSTRIDE 66
__global__ __launch_bounds__(256)
void sample_kernel(const __half* __restrict__ Vh, const float* __restrict__ OA,
                   const float* __restrict__ REF, __half* __restrict__ ACCh)
{
    __shared__ int2 sP[4][Hh * HSTRIDE];   // [token][h*66 + sk*4 + c]

    const int n0  = blockIdx.x * 4;
    const int tid = threadIdx.x;

    // ---- Phase 1: 2 iterations x 256 threads = 4 tokens x 128
#pragma unroll
    for (int it = 0; it < 2; it++) {
        int idx = it * 256 + tid;
        int t  = idx >> 7;
        int r  = idx & 127;
        int n  = n0 + t;
        int b  = n / LQ;
        int h  = r >> 4;
        int sk = r & 15;
        int s  = sk >> 2;

        float lg = OA[(size_t)n * MOA2 + 256 + h * 16 + sk];
        float mx = lg;
#pragma unroll
        for (int o = 8; o > 0; o >>= 1) mx = fmaxf(mx, __shfl_xor_sync(0xffffffffu, mx, o));
        float e = __expf(lg - mx);
        float ssum = e;
#pragma unroll
        for (int o = 8; o > 0; o >>= 1) ssum += __shfl_xor_sync(0xffffffffu, ssum, o);
        float w = e / ssum;

        float refx = REF[(size_t)n * 2 + 0];
        float refy = REF[(size_t)n * 2 + 1];
        float2 oxy = *reinterpret_cast<const float2*>(OA + (size_t)n * MOA2 + h * 32 + sk * 2);

        int wl = c_wl[s], hl = c_hl[s];
        int base_tok = b * LQ + c_offs[s];
        float x = refx * (float)wl + oxy.x - 0.5f;
        float y = refy * (float)hl + oxy.y - 0.5f;
        float x0f = floorf(x), y0f = floorf(y);
        int x0 = (int)x0f, y0 = (int)y0f;
        float wx1 = x - x0f, wx0 = 1.f - wx1;
        float wy1 = y - y0f, wy0 = 1.f - wy1;

#pragma unroll
        for (int c = 0; c < 4; c++) {
            int xi = x0 + (c & 1);
            int yi = y0 + (c >> 1);
            bool valid = (xi >= 0) && (xi < wl) && (yi >= 0) && (yi < hl);
            int xc = min(max(xi, 0), wl - 1);
            int yc = min(max(yi, 0), hl - 1);
            float wc = w * ((c & 1) ? wx1 : wx0) * ((c >> 1) ? wy1 : wy0);
            int off = (base_tok + yc * wl + xc) * (Dm * 2) + h * (DHh * 2);
            int2 pk;
            pk.x = off;
            pk.y = __float_as_int(valid ? wc : 0.f);
            sP[t][h * HSTRIDE + sk * 4 + c] = pk;
        }
    }
    __syncthreads();

    // ---- Phase 2: warp per (token, head-quad); 8 lanes per head; 8 ch/lane
    const int w    = tid >> 5;
    const int lane = tid & 31;
    const int t    = w >> 1;
    const int n    = n0 + t;
    const int h    = (w & 1) * 4 + (lane >> 3);
    const int l8   = lane & 7;
    const char* vb = (const char*)Vh + l8 * 16;   // lane's 8 channels (16 bytes)
    const int2* sPt = &sP[t][h * HSTRIDE];

    float a0 = 0.f, a1 = 0.f, a2 = 0.f, a3 = 0.f;
    float a4 = 0.f, a5 = 0.f, a6 = 0.f, a7 = 0.f;
#pragma unroll 8
    for (int i = 0; i < 64; i++) {
        int2 pk = sPt[i];
        float wg = __int_as_float(pk.y);
        uint4 d = *reinterpret_cast<const uint4*>(vb + pk.x);
        __half2 h0 = *reinterpret_cast<__half2*>(&d.x);
        __half2 h1 = *reinterpret_cast<__half2*>(&d.y);
        __half2 h2 = *reinterpret_cast<__half2*>(&d.z);
        __half2 h3 = *reinterpret_cast<__half2*>(&d.w);
        float2 f0 = __half22float2(h0);
        float2 f1 = __half22float2(h1);
        float2 f2 = __half22float2(h2);
        float2 f3 = __half22float2(h3);
        a0 = fmaf(wg, f0.x, a0); a1 = fmaf(wg, f0.y, a1);
        a2 = fmaf(wg, f1.x, a2); a3 = fmaf(wg, f1.y, a3);
        a4 = fmaf(wg, f2.x, a4); a5 = fmaf(wg, f2.y, a5);
        a6 = fmaf(wg, f3.x, a6); a7 = fmaf(wg, f3.y, a7);
    }
    __half2 o0; o0.x = __float2half(a0); o0.y = __float2half(a1);
    __half2 o1; o1.x = __float2half(a2); o1.y = __float2half(a3);
    __half2 o2; o2.x = __float2half(a4); o2.y = __float2half(a5);
    __half2 o3; o3.x = __float2half(a6); o3.y = __float2half(a7);
    uint4 ov;
    ov.x = *reinterpret_cast<uint32_t*>(&o0);
    ov.y = *reinterpret_cast<uint32_t*>(&o1);
    ov.z = *reinterpret_cast<uint32_t*>(&o2);
    ov.w = *reinterpret_cast<uint32_t*>(&o3);
    *reinterpret_cast<uint4*>(ACCh + (size_t)n * Dm + h * DHh + l8 * 8) = ov;
}

// ---------------------------------------------------------------------------
// Fused residual-add + LayerNorm, fp16 inputs; fp16 and/or fp32 outputs.
// ---------------------------------------------------------------------------
__global__ void add_layernorm_h_kernel(const __half* __restrict__ A, const __half* __restrict__ Bv,
                                       const float* __restrict__ g, const float* __restrict__ be,
                                       __half* __restrict__ outh, float* __restrict__ outf)
{
    int n = blockIdx.x;
    int t = threadIdx.x;
    float v[4];
    float s = 0.f, ss = 0.f;
    const __half2* a2 = reinterpret_cast<const __half2*>(A + (size_t)n * Dm);
    const __half2* b2 = reinterpret_cast<const __half2*>(Bv + (size_t)n * Dm);
#pragma unroll
    for (int i = 0; i < 2; i++) {
        int d2 = t + i * 128;
        float2 fa = __half22float2(a2[d2]);
        float2 fb = __half22float2(b2[d2]);
        float x0 = fa.x + fb.x, x1 = fa.y + fb.y;
        v[i * 2] = x0; v[i * 2 + 1] = x1;
        s += x0 + x1; ss += x0 * x0 + x1 * x1;
    }
#pragma unroll
    for (int o = 16; o > 0; o >>= 1) {
        s  += __shfl_xor_sync(0xffffffffu, s,  o);
        ss += __shfl_xor_sync(0xffffffffu, ss, o);
    }
    __shared__ float sh[8];
    int w = t >> 5, ln = t & 31;
    if (ln == 0) { sh[w] = s; sh[4 + w] = ss; }
    __syncthreads();
    float ts  = sh[0] + sh[1] + sh[2] + sh[3];
    float tss = sh[4] + sh[5] + sh[6] + sh[7];
    float mu  = ts * (1.f / Dm);
    float var = tss * (1.f / Dm) - mu * mu;
    float inv = rsqrtf(var + 1e-5f);
#pragma unroll
    for (int i = 0; i < 2; i++) {
        int d2 = t + i * 128;
        int d = d2 * 2;
        float o0 = (v[i * 2]     - mu) * inv * g[d]     + be[d];
        float o1 = (v[i * 2 + 1] - mu) * inv * g[d + 1] + be[d + 1];
        if (outh) {
            __half2 hv; hv.x = __float2half(o0); hv.y = __float2half(o1);
            *reinterpret_cast<__half2*>(outh + (size_t)n * Dm + d) = hv;
        }
        if (outf) {
            *reinterpret_cast<float2*>(outf + (size_t)n * Dm + d) = make_float2(o0, o1);
        }
    }
}

// ---------------------------------------------------------------------------
// Launch
// ---------------------------------------------------------------------------
extern "C" void kernel_launch(void* const* d_in, const int* in_sizes, int n_in,
                              void* d_out, int out_size)
{
    const float* srcs[4] = {nullptr, nullptr, nullptr, nullptr};
    const float* refs[4] = {nullptr, nullptr, nullptr, nullptr};
    const int src_sz[4] = {Bb * 56 * 56 * Dm, Bb * 28 * 28 * Dm, Bb * 14 * 14 * Dm, Bb * 7 * 7 * Dm};
    const int ref_sz[4] = {Bb * 56 * 56 * 2,  Bb * 28 * 28 * 2,  Bb * 14 * 14 * 2,  Bb * 7 * 7 * 2};
    for (int i = 0; i < 8; i++) {
        int sz = in_sizes[i];
        for (int l = 0; l < 4; l++) {
            if (sz == src_sz[l] && !srcs[l]) { srcs[l] = (const float*)d_in[i]; goto next; }
        }
        for (int l = 0; l < 4; l++) {
            if (sz == ref_sz[l] && !refs[l]) { refs[l] = (const float*)d_in[i]; goto next; }
        }
    next:;
    }

    const float* Wv    = (const float*)d_in[8];
    const float* bv    = (const float*)d_in[9];
    const float* Woff  = (const float*)d_in[10];
    const float* boff  = (const float*)d_in[11];
    const float* Wattn = (const float*)d_in[12];
    const float* battn = (const float*)d_in[13];
    const float* Wo    = (const float*)d_in[14];
    const float* bo    = (const float*)d_in[15];
    const float* W1    = (const float*)d_in[16];
    const float* b1    = (const float*)d_in[17];
    const float* W2    = (const float*)d_in[18];
    const float* b2    = (const float*)d_in[19];
    const float* g1    = (const float*)d_in[20];
    const float* be1   = (const float*)d_in[21];
    const float* g2    = (const float*)d_in[22];
    const float* be2   = (const float*)d_in[23];
    float* out = (float*)d_out;

    float *REF, *OA, *ball;
    __half *Qh, *Vh, *ACCh, *A2h, *Xh, *Hbh, *Yh, *Wah, *Woh, *W1h, *W2h;
    cudaGetSymbolAddress((void**)&REF,  g_REF);
    cudaGetSymbolAddress((void**)&OA,   g_OA);
    cudaGetSymbolAddress((void**)&ball, g_ball);
    cudaGetSymbolAddress((void**)&Qh,   g_Qh);
    cudaGetSymbolAddress((void**)&Vh,   g_Vh);
    cudaGetSymbolAddress((void**)&ACCh, g_ACCh);
    cudaGetSymbolAddress((void**)&A2h,  g_A2h);
    cudaGetSymbolAddress((void**)&Xh,   g_Xh);
    cudaGetSymbolAddress((void**)&Hbh,  g_Hbh);
    cudaGetSymbolAddress((void**)&Yh,   g_Yh);
    cudaGetSymbolAddress((void**)&Wah,  g_Wah);
    cudaGetSymbolAddress((void**)&Woh,  g_Woh);
    cudaGetSymbolAddress((void**)&W1h,  g_W1h);
    cudaGetSymbolAddress((void**)&W2h,  g_W2h);

    cudaFuncSetAttribute(gemm_fp16_kernel<0>, cudaFuncAttributeMaxDynamicSharedMemorySize, SMEM_GEMM);
    cudaFuncSetAttribute(gemm_fp16_kernel<1>, cudaFuncAttributeMaxDynamicSharedMemorySize, SMEM_GEMM);
    cudaFuncSetAttribute(gemm_fp16_kernel<2>, cudaFuncAttributeMaxDynamicSharedMemorySize, SMEM_GEMM);
    cudaFuncSetAttribute(gemm_fp16_kernel<3>, cudaFuncAttributeMaxDynamicSharedMemorySize, SMEM_GEMM);

    const int rowBlocks = (NTOK + 127) / 128;   // 131
    dim3 blk(256);

    // 0: ALL weight prep in one kernel
    {
        int total = N_WA + N_W1 + N_W2 + N_WO;
        prep_w_kernel<<<(total + 255) / 256, 256>>>(Wv, Woff, Wattn, bv, boff, battn,
                                                    W1, W2, Wo, Wah, ball, W1h, W2h, Woh);
    }
    // 1: pack (Q + REF folded)
    {
        int total = NTOK * (Dm / 4);
        pack_kernel<<<(total + 255) / 256, 256>>>(srcs[0], srcs[1], srcs[2], srcs[3],
                                                  refs[0], refs[1], refs[2], refs[3], Qh, REF);
    }
    // 2: [Vh | OA] = Q @ [Wv|Woff|Wattn] + bias
    gemm_fp16_kernel<2><<<dim3(MVOA / 128, rowBlocks), blk, SMEM_GEMM>>>(Qh, Wah, ball, Vh, OA, NTOK, Dm, MVOA);
    // 3: two-phase sampling (4 tokens/block) -> ACCh
    sample_kernel<<<NTOK / 4, 256>>>(Vh, OA, REF, ACCh);
    // 4: A2h = ACC @ Wo + bo  (fp16 out)
    gemm_fp16_kernel<3><<<dim3(Dm / 128, rowBlocks), blk, SMEM_GEMM>>>(ACCh, Woh, bo, A2h, nullptr, NTOK, Dm, Dm);
    // 5: Xh = LN(Qh + A2h)
    add_layernorm_h_kernel<<<NTOK, 128>>>(Qh, A2h, g1, be1, Xh, nullptr);
    // 6: Hbh = fp16(relu(X @ W1 + b1))
    gemm_fp16_kernel<1><<<dim3(DFFm / 128, rowBlocks), blk, SMEM_GEMM>>>(Xh, W1h, b1, Hbh, nullptr, NTOK, Dm, DFFm);
    // 7: Yh = Hb @ W2 + b2  (fp16 out)
    gemm_fp16_kernel<3><<<dim3(Dm / 128, rowBlocks), blk, SMEM_GEMM>>>(Hbh, W2h, b2, Yh, nullptr, NTOK, DFFm, Dm);
    // 8: out = LN(Xh + Yh)  (fp32 to d_out)
    add_layernorm_h_kernel<<<NTOK, 128>>>(Xh, Yh, g2, be2, nullptr, out);
}